// round 2
// baseline (speedup 1.0000x reference)
#include <cuda_runtime.h>

#define NN 100000
#define NE 1250000

// ---------------- device scratch (no allocs allowed) ----------------
__device__ __align__(16) float g_w[(size_t)NE * 64];     // per-edge weights [E][64]
__device__ __align__(16) float g_agg[(size_t)NN * 64];   // scatter accumulator [N][64]
__device__ float g_deg[NN];
__device__ float g_invdeg[NN];
__device__ int   g_idx64;                                // 1 if edge_index is int64

__device__ __forceinline__ float sigm(float x) { return 1.f / (1.f + expf(-x)); }

__device__ __forceinline__ void red_add_v4(float4* addr, float4 v) {
    asm volatile("red.global.add.v4.f32 [%0], {%1, %2, %3, %4};"
                 :: "l"(addr), "f"(v.x), "f"(v.y), "f"(v.z), "f"(v.w) : "memory");
}

// ---------------- dtype detection for edge_index ----------------
__global__ void detect_kernel(const int* __restrict__ p) {
    __shared__ int nz;
    if (threadIdx.x == 0) nz = 0;
    __syncthreads();
    // int64 little-endian: every odd 32-bit word is a (zero) high word.
    if (p[2 * threadIdx.x + 1] != 0) atomicOr(&nz, 1);
    __syncthreads();
    if (threadIdx.x == 0) g_idx64 = (nz == 0) ? 1 : 0;
}

// ---------------- trivial kernels ----------------
__global__ void copy_hx_kernel(const float* __restrict__ hx, float* __restrict__ out, int N) {
    int idx = blockIdx.x * blockDim.x + threadIdx.x;
    if (idx < N * 64) {
        int n = idx >> 6, k = idx & 63;
        out[(size_t)n * 256 + k] = hx[idx];
    }
}

__global__ void zero_agg_kernel() {
    size_t idx = (size_t)blockIdx.x * blockDim.x + threadIdx.x;
    if (idx < (size_t)NN * 64 / 4)
        ((float4*)g_agg)[idx] = make_float4(0.f, 0.f, 0.f, 0.f);
}

__global__ void zero_deg_kernel() {
    int i = blockIdx.x * blockDim.x + threadIdx.x;
    if (i < NN) g_deg[i] = 0.f;
}

__global__ void deg_kernel(const void* __restrict__ eidx, int E) {
    int e = blockIdx.x * blockDim.x + threadIdx.x;
    if (e >= E) return;
    long long d;
    if (g_idx64) d = ((const long long*)eidx)[e];
    else         d = (long long)((const int*)eidx)[e];
    atomicAdd(&g_deg[d], 1.0f);
}

__global__ void invdeg_kernel() {
    int i = blockIdx.x * blockDim.x + threadIdx.x;
    if (i < NN) g_invdeg[i] = 1.0f / fmaxf(g_deg[i], 1.0f);
}

// ---------------- fnet: per-edge MLP 13 -> 64 -> 64 -> 64 ----------------
// Block: 256 threads, 128 edges. Register-tiled micro-GEMM, 4 edges x 8 outs / thread.
#define FNET_SMEM ((4096 + 64 + 8448 + 8448) * 4)

__global__ __launch_bounds__(256, 2) void fnet_kernel(
    const float* __restrict__ ef,
    const float* __restrict__ fW1, const float* __restrict__ fb1,
    const float* __restrict__ fW2, const float* __restrict__ fb2,
    const float* __restrict__ fW3, const float* __restrict__ fb3,
    int E)
{
    extern __shared__ float sm[];
    float* sW  = sm;            // [k][o]  64*64
    float* sB  = sW + 4096;     // 64
    float* sA  = sB + 64;       // actT [k][e], stride 132
    float* sA2 = sA + 8448;     // actT next

    const int tx = threadIdx.x;
    const int e0 = blockIdx.x * 128;
    const int o0 = (tx & 7) * 8;
    const int el = (tx >> 3) * 4;

    // stage x transposed: sA[k*132 + e]
    for (int idx = tx; idx < 128 * 13; idx += 256) {
        int e = idx / 13, k = idx - e * 13;
        float v = 0.f;
        if (e0 + e < E) v = ef[(size_t)e0 * 13 + idx];
        sA[k * 132 + e] = v;
    }
    for (int idx = tx; idx < 64 * 13; idx += 256) {
        int o = idx / 13, k = idx - o * 13;
        sW[k * 64 + o] = fW1[idx];
    }
    if (tx < 64) sB[tx] = fb1[tx];
    __syncthreads();

    float acc[4][8];

    // ---- layer 1 (K = 13) ----
    #pragma unroll
    for (int i = 0; i < 4; i++)
        #pragma unroll
        for (int j = 0; j < 8; j++) acc[i][j] = sB[o0 + j];
    #pragma unroll
    for (int k = 0; k < 13; k++) {
        float4 a  = *(const float4*)(sA + k * 132 + el);
        float4 w0 = *(const float4*)(sW + k * 64 + o0);
        float4 w1 = *(const float4*)(sW + k * 64 + o0 + 4);
        float av[4] = {a.x, a.y, a.z, a.w};
        float wv[8] = {w0.x, w0.y, w0.z, w0.w, w1.x, w1.y, w1.z, w1.w};
        #pragma unroll
        for (int i = 0; i < 4; i++)
            #pragma unroll
            for (int j = 0; j < 8; j++) acc[i][j] += av[i] * wv[j];
    }
    #pragma unroll
    for (int j = 0; j < 8; j++) {
        float4 v;
        v.x = fmaxf(acc[0][j], 0.f); v.y = fmaxf(acc[1][j], 0.f);
        v.z = fmaxf(acc[2][j], 0.f); v.w = fmaxf(acc[3][j], 0.f);
        *(float4*)(sA2 + (o0 + j) * 132 + el) = v;
    }
    __syncthreads();

    // ---- layer 2 (K = 64) ----
    for (int idx = tx; idx < 4096; idx += 256) {
        int o = idx >> 6, k = idx & 63;
        sW[k * 64 + o] = fW2[idx];
    }
    if (tx < 64) sB[tx] = fb2[tx];
    __syncthreads();

    #pragma unroll
    for (int i = 0; i < 4; i++)
        #pragma unroll
        for (int j = 0; j < 8; j++) acc[i][j] = sB[o0 + j];
    #pragma unroll 8
    for (int k = 0; k < 64; k++) {
        float4 a  = *(const float4*)(sA2 + k * 132 + el);
        float4 w0 = *(const float4*)(sW + k * 64 + o0);
        float4 w1 = *(const float4*)(sW + k * 64 + o0 + 4);
        float av[4] = {a.x, a.y, a.z, a.w};
        float wv[8] = {w0.x, w0.y, w0.z, w0.w, w1.x, w1.y, w1.z, w1.w};
        #pragma unroll
        for (int i = 0; i < 4; i++)
            #pragma unroll
            for (int j = 0; j < 8; j++) acc[i][j] += av[i] * wv[j];
    }
    #pragma unroll
    for (int j = 0; j < 8; j++) {
        float4 v;
        v.x = fmaxf(acc[0][j], 0.f); v.y = fmaxf(acc[1][j], 0.f);
        v.z = fmaxf(acc[2][j], 0.f); v.w = fmaxf(acc[3][j], 0.f);
        *(float4*)(sA + (o0 + j) * 132 + el) = v;
    }
    __syncthreads();

    // ---- layer 3 (K = 64, no relu) ----
    for (int idx = tx; idx < 4096; idx += 256) {
        int o = idx >> 6, k = idx & 63;
        sW[k * 64 + o] = fW3[idx];
    }
    if (tx < 64) sB[tx] = fb3[tx];
    __syncthreads();

    #pragma unroll
    for (int i = 0; i < 4; i++)
        #pragma unroll
        for (int j = 0; j < 8; j++) acc[i][j] = sB[o0 + j];
    #pragma unroll 8
    for (int k = 0; k < 64; k++) {
        float4 a  = *(const float4*)(sA + k * 132 + el);
        float4 w0 = *(const float4*)(sW + k * 64 + o0);
        float4 w1 = *(const float4*)(sW + k * 64 + o0 + 4);
        float av[4] = {a.x, a.y, a.z, a.w};
        float wv[8] = {w0.x, w0.y, w0.z, w0.w, w1.x, w1.y, w1.z, w1.w};
        #pragma unroll
        for (int i = 0; i < 4; i++)
            #pragma unroll
            for (int j = 0; j < 8; j++) acc[i][j] += av[i] * wv[j];
    }
    #pragma unroll
    for (int i = 0; i < 4; i++) {
        int e = e0 + el + i;
        if (e < E) {
            float4 v0 = make_float4(acc[i][0], acc[i][1], acc[i][2], acc[i][3]);
            float4 v1 = make_float4(acc[i][4], acc[i][5], acc[i][6], acc[i][7]);
            *(float4*)(g_w + (size_t)e * 64 + o0)     = v0;
            *(float4*)(g_w + (size_t)e * 64 + o0 + 4) = v1;
        }
    }
}

// ---------------- gather-multiply-scatter (per repeat) ----------------
__global__ void scatter_kernel(const void* __restrict__ eidx,
                               const float* __restrict__ out, int t, int E)
{
    long long idx = (long long)blockIdx.x * blockDim.x + threadIdx.x;
    if (idx >= (long long)E * 4) return;
    int e = (int)(idx >> 2);
    int q = (int)(idx & 3);
    long long d, s;
    if (g_idx64) {
        const long long* p = (const long long*)eidx;
        d = p[e]; s = p[E + e];
    } else {
        const int* p = (const int*)eidx;
        d = p[e]; s = p[E + e];
    }
    const float4* hv = (const float4*)(out + s * 256 + t * 64);
    const float4* wv = (const float4*)(g_w + (size_t)e * 64);
    float4*       av = (float4*)(g_agg + d * 64);
    #pragma unroll
    for (int j = 0; j < 4; j++) {
        int c = j * 4 + q;   // warp-contiguous within each j step (full sectors)
        float4 h = __ldg(hv + c);
        float4 w = __ldg(wv + c);
        float4 m = make_float4(h.x * w.x, h.y * w.y, h.z * w.z, h.w * w.w);
        red_add_v4(av + c, m);
    }
}

// ---------------- fused GRU node update (per repeat) ----------------
// Block: 256 threads, 64 nodes. All GEMMs + instance-norm + gates fused.
#define NODE_SMEM ((4352 + 4352 + 4096 + 12352 + 12352 + 64 + 192 + 192 + 256) * 4)

__global__ __launch_bounds__(256, 1) void node_kernel(
    float* __restrict__ out,
    const float* __restrict__ Wih, const float* __restrict__ Whh,
    const float* __restrict__ bih, const float* __restrict__ bhh,
    const float* __restrict__ Wig, const float* __restrict__ big,
    int t, int N)
{
    extern __shared__ float sm[];
    float* sHx  = sm;              // hxT [k][n], stride 68
    float* sInp = sHx + 4352;      // inpT [k][n], stride 68
    float* sW   = sInp + 4352;     // weight chunk [k][o] 64*64
    float* sGI  = sW + 4096;       // [n][192], stride 193
    float* sGH  = sGI + 12352;
    float* sBig = sGH + 12352;     // 64
    float* sBih = sBig + 64;       // 192
    float* sBhh = sBih + 192;      // 192
    float* sStat = sBhh + 192;     // [muI 64][rsI 64][muH 64][rsH 64]
    float* sRed = sW;              // reuse weight buffer after GEMMs

    const int tx = threadIdx.x;
    const int n0 = blockIdx.x * 64;
    const int toff = t * 64;
    const int o0 = (tx & 7) * 8;
    const int nl = (tx >> 3) * 2;

    // stage hx transposed
    for (int idx = tx; idx < 4096; idx += 256) {
        int n = idx >> 6, k = idx & 63;
        float v = (n0 + n < N) ? out[(size_t)(n0 + n) * 256 + toff + k] : 0.f;
        sHx[k * 68 + n] = v;
    }
    // stage Wig transposed + biases
    for (int idx = tx; idx < 4096; idx += 256) {
        int o = idx >> 6, k = idx & 63;
        sW[k * 64 + o] = Wig[idx];
    }
    if (tx < 64)  sBig[tx] = big[tx];
    if (tx < 192) { sBih[tx] = bih[tx]; sBhh[tx] = bhh[tx]; }
    __syncthreads();

    // ---- GEMM: ig = sigmoid(hx @ Wig^T + big); inp = ig * agg * invdeg ----
    {
        float acc[2][8];
        #pragma unroll
        for (int i = 0; i < 2; i++)
            #pragma unroll
            for (int j = 0; j < 8; j++) acc[i][j] = sBig[o0 + j];
        #pragma unroll 8
        for (int k = 0; k < 64; k++) {
            float2 a  = *(const float2*)(sHx + k * 68 + nl);
            float4 w0 = *(const float4*)(sW + k * 64 + o0);
            float4 w1 = *(const float4*)(sW + k * 64 + o0 + 4);
            float av[2] = {a.x, a.y};
            float wv[8] = {w0.x, w0.y, w0.z, w0.w, w1.x, w1.y, w1.z, w1.w};
            #pragma unroll
            for (int i = 0; i < 2; i++)
                #pragma unroll
                for (int j = 0; j < 8; j++) acc[i][j] += av[i] * wv[j];
        }
        #pragma unroll
        for (int i = 0; i < 2; i++) {
            int gn = n0 + nl + i;
            float invd = 0.f;
            float4 a0 = make_float4(0, 0, 0, 0), a1 = make_float4(0, 0, 0, 0);
            if (gn < N) {
                invd = g_invdeg[gn];
                a0 = *(const float4*)(g_agg + (size_t)gn * 64 + o0);
                a1 = *(const float4*)(g_agg + (size_t)gn * 64 + o0 + 4);
            }
            float ag[8] = {a0.x, a0.y, a0.z, a0.w, a1.x, a1.y, a1.z, a1.w};
            #pragma unroll
            for (int j = 0; j < 8; j++) {
                float v = sigm(acc[i][j]) * ag[j] * invd;
                sInp[(o0 + j) * 68 + nl + i] = v;
            }
        }
    }
    __syncthreads();

    // ---- GI = inp @ Wih^T (3 chunks of 64 outputs) ----
    for (int c = 0; c < 3; c++) {
        for (int idx = tx; idx < 4096; idx += 256) {
            int o = idx >> 6, k = idx & 63;
            sW[k * 64 + o] = Wih[(size_t)c * 4096 + idx];
        }
        __syncthreads();
        float ac[2][8];
        #pragma unroll
        for (int i = 0; i < 2; i++)
            #pragma unroll
            for (int j = 0; j < 8; j++) ac[i][j] = 0.f;
        #pragma unroll 8
        for (int k = 0; k < 64; k++) {
            float2 a  = *(const float2*)(sInp + k * 68 + nl);
            float4 w0 = *(const float4*)(sW + k * 64 + o0);
            float4 w1 = *(const float4*)(sW + k * 64 + o0 + 4);
            float av[2] = {a.x, a.y};
            float wv[8] = {w0.x, w0.y, w0.z, w0.w, w1.x, w1.y, w1.z, w1.w};
            #pragma unroll
            for (int i = 0; i < 2; i++)
                #pragma unroll
                for (int j = 0; j < 8; j++) ac[i][j] += av[i] * wv[j];
        }
        #pragma unroll
        for (int i = 0; i < 2; i++)
            #pragma unroll
            for (int j = 0; j < 8; j++)
                sGI[(nl + i) * 193 + c * 64 + o0 + j] = ac[i][j];
        __syncthreads();
    }

    // ---- GH = hx @ Whh^T (3 chunks) ----
    for (int c = 0; c < 3; c++) {
        for (int idx = tx; idx < 4096; idx += 256) {
            int o = idx >> 6, k = idx & 63;
            sW[k * 64 + o] = Whh[(size_t)c * 4096 + idx];
        }
        __syncthreads();
        float ac[2][8];
        #pragma unroll
        for (int i = 0; i < 2; i++)
            #pragma unroll
            for (int j = 0; j < 8; j++) ac[i][j] = 0.f;
        #pragma unroll 8
        for (int k = 0; k < 64; k++) {
            float2 a  = *(const float2*)(sHx + k * 68 + nl);
            float4 w0 = *(const float4*)(sW + k * 64 + o0);
            float4 w1 = *(const float4*)(sW + k * 64 + o0 + 4);
            float av[2] = {a.x, a.y};
            float wv[8] = {w0.x, w0.y, w0.z, w0.w, w1.x, w1.y, w1.z, w1.w};
            #pragma unroll
            for (int i = 0; i < 2; i++)
                #pragma unroll
                for (int j = 0; j < 8; j++) ac[i][j] += av[i] * wv[j];
        }
        #pragma unroll
        for (int i = 0; i < 2; i++)
            #pragma unroll
            for (int j = 0; j < 8; j++)
                sGH[(nl + i) * 193 + c * 64 + o0 + j] = ac[i][j];
        __syncthreads();
    }

    // ---- instance-norm stats (per node, over 192 features) ----
    {
        int part = tx >> 6;    // 0,1: GI halves; 2,3: GH halves
        int n = tx & 63;
        const float* row = (part < 2) ? (sGI + n * 193) : (sGH + n * 193);
        int off = (part & 1) * 96;
        float s = 0.f, q = 0.f;
        #pragma unroll 4
        for (int u = 0; u < 96; u++) { float v = row[off + u]; s += v; q += v * v; }
        sRed[part * 64 + n]       = s;
        sRed[256 + part * 64 + n] = q;
    }
    __syncthreads();
    if (tx < 128) {
        int n = tx & 63;
        int isH = tx >> 6;
        int pb = isH * 2;
        float s = sRed[pb * 64 + n] + sRed[(pb + 1) * 64 + n];
        float q = sRed[256 + pb * 64 + n] + sRed[256 + (pb + 1) * 64 + n];
        float mu = s * (1.f / 192.f);
        float var = q * (1.f / 192.f) - mu * mu;
        sStat[isH * 128 + n]      = mu;
        sStat[isH * 128 + 64 + n] = rsqrtf(var + 1e-5f);
    }
    __syncthreads();

    // ---- gates + hx update ----
    {
        int h = tx & 63;
        int nb = tx >> 6;
        #pragma unroll
        for (int i = 0; i < 16; i++) {
            int n = nb * 16 + i;
            int gn = n0 + n;
            if (gn >= N) continue;
            float muI = sStat[n],       rsI = sStat[64 + n];
            float muH = sStat[128 + n], rsH = sStat[192 + n];
            const float* gi = sGI + n * 193;
            const float* gh = sGH + n * 193;
            float i_r = (gi[h]        - muI) * rsI;
            float i_i = (gi[64 + h]   - muI) * rsI;
            float i_n = (gi[128 + h]  - muI) * rsI;
            float h_r = (gh[h]        - muH) * rsH;
            float h_i = (gh[64 + h]   - muH) * rsH;
            float h_n = (gh[128 + h]  - muH) * rsH;
            float r  = sigm(i_r + sBih[h]      + h_r + sBhh[h]);
            float z  = sigm(i_i + sBih[64 + h] + h_i + sBhh[64 + h]);
            float ng = tanhf(i_n + sBih[128 + h] + r * (h_n + sBhh[128 + h]));
            float hxo = sHx[h * 68 + n];
            out[(size_t)gn * 256 + toff + 64 + h] = ng + z * (hxo - ng);
        }
    }
}

// ---------------- launcher ----------------
extern "C" void kernel_launch(void* const* d_in, const int* in_sizes, int n_in,
                              void* d_out, int out_size)
{
    const float* hx  = (const float*)d_in[0];
    const void*  eix = d_in[1];
    const float* ef  = (const float*)d_in[2];
    const float* fW1 = (const float*)d_in[3];
    const float* fb1 = (const float*)d_in[4];
    const float* fW2 = (const float*)d_in[5];
    const float* fb2 = (const float*)d_in[6];
    const float* fW3 = (const float*)d_in[7];
    const float* fb3 = (const float*)d_in[8];
    const float* Wih = (const float*)d_in[9];
    const float* Whh = (const float*)d_in[10];
    const float* bih = (const float*)d_in[11];
    const float* bhh = (const float*)d_in[12];
    const float* Wig = (const float*)d_in[13];
    const float* big = (const float*)d_in[14];
    float* out = (float*)d_out;

    const int N = in_sizes[0] / 64;
    const int E = in_sizes[2] / 13;

    cudaFuncSetAttribute(fnet_kernel, cudaFuncAttributeMaxDynamicSharedMemorySize, FNET_SMEM);
    cudaFuncSetAttribute(node_kernel, cudaFuncAttributeMaxDynamicSharedMemorySize, NODE_SMEM);

    detect_kernel<<<1, 256>>>((const int*)eix);
    copy_hx_kernel<<<(N * 64 + 255) / 256, 256>>>(hx, out, N);
    zero_deg_kernel<<<(NN + 255) / 256, 256>>>();
    deg_kernel<<<(E + 255) / 256, 256>>>(eix, E);
    invdeg_kernel<<<(NN + 255) / 256, 256>>>();
    fnet_kernel<<<(E + 127) / 128, 256, FNET_SMEM>>>(ef, fW1, fb1, fW2, fb2, fW3, fb3, E);

    for (int t = 0; t < 3; t++) {
        zero_agg_kernel<<<((NN * 64 / 4) + 255) / 256, 256>>>();
        scatter_kernel<<<(int)(((long long)E * 4 + 255) / 256), 256>>>(eix, out, t, E);
        node_kernel<<<(N + 63) / 64, 256, NODE_SMEM>>>(out, Wih, Whh, bih, bhh, Wig, big, t, N);
    }
}

// round 4
// speedup vs baseline: 2.3203x; 2.3203x over previous
#include <cuda_runtime.h>
#include <cstdint>

#define NN 100000
#define NE 1250000

// ---------------- device scratch (no allocs allowed) ----------------
__device__ __align__(16) float g_w[(size_t)NE * 64];     // per-edge weights [E][64]
__device__ __align__(16) float g_agg[(size_t)NN * 64];   // scatter accumulator [N][64]
__device__ float g_deg[NN];
__device__ float g_invdeg[NN];
__device__ int   g_idx64;                                // 1 if edge_index is int64

__device__ __forceinline__ float sigm(float x) { return 1.f / (1.f + expf(-x)); }

__device__ __forceinline__ void red_add_v4(float4* addr, float4 v) {
    asm volatile("red.global.add.v4.f32 [%0], {%1, %2, %3, %4};"
                 :: "l"(addr), "f"(v.x), "f"(v.y), "f"(v.z), "f"(v.w) : "memory");
}

__device__ __forceinline__ uint32_t f2tf32(float x) {
    uint32_t u;
    asm("cvt.rna.tf32.f32 %0, %1;" : "=r"(u) : "f"(x));
    return u;
}

// D(16x8) += A(16x8) * B(8x8)^T-ish:  D[m][n] = sum_k A[m][k] * W[n][k]
__device__ __forceinline__ void mma_tf32(float& c0, float& c1, float& c2, float& c3,
                                         uint32_t a0, uint32_t a1, uint32_t a2, uint32_t a3,
                                         uint32_t b0, uint32_t b1)
{
    asm volatile("mma.sync.aligned.m16n8k8.row.col.f32.tf32.tf32.f32 "
                 "{%0,%1,%2,%3}, {%4,%5,%6,%7}, {%8,%9}, {%0,%1,%2,%3};"
                 : "+f"(c0), "+f"(c1), "+f"(c2), "+f"(c3)
                 : "r"(a0), "r"(a1), "r"(a2), "r"(a3), "r"(b0), "r"(b1));
}

// ---------------- dtype detection for edge_index ----------------
__global__ void detect_kernel(const int* __restrict__ p) {
    __shared__ int nz;
    if (threadIdx.x == 0) nz = 0;
    __syncthreads();
    if (p[2 * threadIdx.x + 1] != 0) atomicOr(&nz, 1);
    __syncthreads();
    if (threadIdx.x == 0) g_idx64 = (nz == 0) ? 1 : 0;
}

// ---------------- trivial kernels ----------------
__global__ void copy_hx_kernel(const float* __restrict__ hx, float* __restrict__ out, int N) {
    int idx = blockIdx.x * blockDim.x + threadIdx.x;
    if (idx < N * 64) {
        int n = idx >> 6, k = idx & 63;
        out[(size_t)n * 256 + k] = hx[idx];
    }
}

__global__ void zero_agg_kernel() {
    size_t idx = (size_t)blockIdx.x * blockDim.x + threadIdx.x;
    if (idx < (size_t)NN * 64 / 4)
        ((float4*)g_agg)[idx] = make_float4(0.f, 0.f, 0.f, 0.f);
}

__global__ void zero_deg_kernel() {
    int i = blockIdx.x * blockDim.x + threadIdx.x;
    if (i < NN) g_deg[i] = 0.f;
}

__global__ void deg_kernel(const void* __restrict__ eidx, int E) {
    int e = blockIdx.x * blockDim.x + threadIdx.x;
    if (e >= E) return;
    long long d;
    if (g_idx64) d = ((const long long*)eidx)[e];
    else         d = (long long)((const int*)eidx)[e];
    atomicAdd(&g_deg[d], 1.0f);
}

__global__ void invdeg_kernel() {
    int i = blockIdx.x * blockDim.x + threadIdx.x;
    if (i < NN) g_invdeg[i] = 1.0f / fmaxf(g_deg[i], 1.0f);
}

// ---------------- fnet via mma.sync tf32 ----------------
// Block: 256 threads (8 warps), 128 edges. Warp w owns rows 16w..16w+15.
// All layers computed in-place in sX (per-warp row ownership -> no block syncs).
#define FS 68
#define F_X   0
#define F_W1  (128 * FS)             /* 8704  */
#define F_W2  (F_W1 + 64 * FS)       /* 13056 */
#define F_W3  (F_W2 + 64 * FS)       /* 17408 */
#define F_B   (F_W3 + 64 * FS)       /* 21760 */
#define FNET_FLOATS (F_B + 192)      /* 21952 */
#define FNET_SMEM (FNET_FLOATS * 4)  /* 87808 B */

__global__ __launch_bounds__(256, 2) void fnet_mma_kernel(
    const float* __restrict__ ef,
    const float* __restrict__ fW1, const float* __restrict__ fb1,
    const float* __restrict__ fW2, const float* __restrict__ fb2,
    const float* __restrict__ fW3, const float* __restrict__ fb3,
    int E)
{
    extern __shared__ float sm[];
    uint32_t* uX  = (uint32_t*)(sm + F_X);
    uint32_t* uW1 = (uint32_t*)(sm + F_W1);
    uint32_t* uW2 = (uint32_t*)(sm + F_W2);
    uint32_t* uW3 = (uint32_t*)(sm + F_W3);
    float*    sB  = sm + F_B;

    const int tid = threadIdx.x;
    const int wid = tid >> 5, lane = tid & 31;
    const int g = lane >> 2, q = lane & 3;
    const int e0 = blockIdx.x * 128;
    const int r0 = wid * 16;
    const int rA = r0 + g, rB = r0 + 8 + g;

    // stage X (K padded to 16, tf32)
    for (int idx = tid; idx < 128 * 16; idx += 256) {
        int e = idx >> 4, k = idx & 15;
        float v = (k < 13 && e0 + e < E) ? ef[(size_t)(e0 + e) * 13 + k] : 0.f;
        uX[e * FS + k] = f2tf32(v);
    }
    // stage W1 [64 x 16] (pad k 13..15 with 0)
    for (int idx = tid; idx < 64 * 16; idx += 256) {
        int o = idx >> 4, k = idx & 15;
        uW1[o * FS + k] = (k < 13) ? f2tf32(fW1[o * 13 + k]) : 0u;
    }
    // stage W2 / W3 [64 x 64]
    for (int idx = tid; idx < 4096; idx += 256) {
        int o = idx >> 6, k = idx & 63;
        uW2[o * FS + k] = f2tf32(fW2[idx]);
        uW3[o * FS + k] = f2tf32(fW3[idx]);
    }
    if (tid < 64) { sB[tid] = fb1[tid]; sB[64 + tid] = fb2[tid]; sB[128 + tid] = fb3[tid]; }
    __syncthreads();

    float acc[8][4];

    // ---- layer 1 (K = 16) ----
    #pragma unroll
    for (int j = 0; j < 8; j++) {
        int cb = j * 8 + 2 * q;
        acc[j][0] = acc[j][2] = sB[cb];
        acc[j][1] = acc[j][3] = sB[cb + 1];
    }
    #pragma unroll
    for (int k0 = 0; k0 < 2; k0++) {
        uint32_t a0 = uX[rA * FS + 8 * k0 + q];
        uint32_t a1 = uX[rB * FS + 8 * k0 + q];
        uint32_t a2 = uX[rA * FS + 8 * k0 + q + 4];
        uint32_t a3 = uX[rB * FS + 8 * k0 + q + 4];
        #pragma unroll
        for (int j = 0; j < 8; j++) {
            uint32_t b0 = uW1[(8 * j + g) * FS + 8 * k0 + q];
            uint32_t b1 = uW1[(8 * j + g) * FS + 8 * k0 + q + 4];
            mma_tf32(acc[j][0], acc[j][1], acc[j][2], acc[j][3], a0, a1, a2, a3, b0, b1);
        }
    }
    #pragma unroll
    for (int j = 0; j < 8; j++) {
        int cb = j * 8 + 2 * q;
        uX[rA * FS + cb]     = f2tf32(fmaxf(acc[j][0], 0.f));
        uX[rA * FS + cb + 1] = f2tf32(fmaxf(acc[j][1], 0.f));
        uX[rB * FS + cb]     = f2tf32(fmaxf(acc[j][2], 0.f));
        uX[rB * FS + cb + 1] = f2tf32(fmaxf(acc[j][3], 0.f));
    }
    __syncwarp();

    // ---- layer 2 (K = 64, relu) ----
    #pragma unroll
    for (int j = 0; j < 8; j++) {
        int cb = j * 8 + 2 * q;
        acc[j][0] = acc[j][2] = sB[64 + cb];
        acc[j][1] = acc[j][3] = sB[64 + cb + 1];
    }
    #pragma unroll
    for (int k0 = 0; k0 < 8; k0++) {
        uint32_t a0 = uX[rA * FS + 8 * k0 + q];
        uint32_t a1 = uX[rB * FS + 8 * k0 + q];
        uint32_t a2 = uX[rA * FS + 8 * k0 + q + 4];
        uint32_t a3 = uX[rB * FS + 8 * k0 + q + 4];
        #pragma unroll
        for (int j = 0; j < 8; j++) {
            uint32_t b0 = uW2[(8 * j + g) * FS + 8 * k0 + q];
            uint32_t b1 = uW2[(8 * j + g) * FS + 8 * k0 + q + 4];
            mma_tf32(acc[j][0], acc[j][1], acc[j][2], acc[j][3], a0, a1, a2, a3, b0, b1);
        }
    }
    __syncwarp();   // everyone done reading X (layer-2 inputs) before overwrite
    #pragma unroll
    for (int j = 0; j < 8; j++) {
        int cb = j * 8 + 2 * q;
        uX[rA * FS + cb]     = f2tf32(fmaxf(acc[j][0], 0.f));
        uX[rA * FS + cb + 1] = f2tf32(fmaxf(acc[j][1], 0.f));
        uX[rB * FS + cb]     = f2tf32(fmaxf(acc[j][2], 0.f));
        uX[rB * FS + cb + 1] = f2tf32(fmaxf(acc[j][3], 0.f));
    }
    __syncwarp();

    // ---- layer 3 (K = 64, no relu, fp32 out) ----
    #pragma unroll
    for (int j = 0; j < 8; j++) {
        int cb = j * 8 + 2 * q;
        acc[j][0] = acc[j][2] = sB[128 + cb];
        acc[j][1] = acc[j][3] = sB[128 + cb + 1];
    }
    #pragma unroll
    for (int k0 = 0; k0 < 8; k0++) {
        uint32_t a0 = uX[rA * FS + 8 * k0 + q];
        uint32_t a1 = uX[rB * FS + 8 * k0 + q];
        uint32_t a2 = uX[rA * FS + 8 * k0 + q + 4];
        uint32_t a3 = uX[rB * FS + 8 * k0 + q + 4];
        #pragma unroll
        for (int j = 0; j < 8; j++) {
            uint32_t b0 = uW3[(8 * j + g) * FS + 8 * k0 + q];
            uint32_t b1 = uW3[(8 * j + g) * FS + 8 * k0 + q + 4];
            mma_tf32(acc[j][0], acc[j][1], acc[j][2], acc[j][3], a0, a1, a2, a3, b0, b1);
        }
    }
    __syncwarp();
    {
        float* sX = sm + F_X;
        #pragma unroll
        for (int j = 0; j < 8; j++) {
            int cb = j * 8 + 2 * q;
            sX[rA * FS + cb]     = acc[j][0];
            sX[rA * FS + cb + 1] = acc[j][1];
            sX[rB * FS + cb]     = acc[j][2];
            sX[rB * FS + cb + 1] = acc[j][3];
        }
    }
    __syncthreads();

    // coalesced store to g_w
    {
        float4* gw = (float4*)(g_w + (size_t)e0 * 64);
        const float* sX = sm + F_X;
        #pragma unroll
        for (int i = 0; i < 8; i++) {
            int gidx = i * 256 + tid;       // 0..2047 float4s
            int r = gidx >> 4, c4 = gidx & 15;
            if (e0 + r < E)
                gw[gidx] = *(const float4*)(sX + r * FS + c4 * 4);
        }
    }
}

// ---------------- gather-multiply-scatter (per repeat) ----------------
__global__ void scatter_kernel(const void* __restrict__ eidx,
                               const float* __restrict__ out, int t, int E)
{
    long long idx = (long long)blockIdx.x * blockDim.x + threadIdx.x;
    if (idx >= (long long)E * 4) return;
    int e = (int)(idx >> 2);
    int q = (int)(idx & 3);
    long long d, s;
    if (g_idx64) {
        const long long* p = (const long long*)eidx;
        d = p[e]; s = p[E + e];
    } else {
        const int* p = (const int*)eidx;
        d = p[e]; s = p[E + e];
    }
    const float4* hv = (const float4*)(out + s * 256 + t * 64);
    const float4* wv = (const float4*)(g_w + (size_t)e * 64);
    float4*       av = (float4*)(g_agg + d * 64);
    #pragma unroll
    for (int j = 0; j < 4; j++) {
        int c = j * 4 + q;
        float4 h = __ldg(hv + c);
        float4 w = __ldg(wv + c);
        float4 m = make_float4(h.x * w.x, h.y * w.y, h.z * w.z, h.w * w.w);
        red_add_v4(av + c, m);
    }
}

// ---------------- fused GRU node update, tf32 mma (per repeat) ----------------
// Block: 256 threads (8 warps), 64 nodes. warp w: rows (w&3)*16, n-half (w>>2)*32.
#define N_HX   0
#define N_INP  (N_HX + 64 * FS)        /* 4352  */
#define N_W    (N_INP + 64 * FS)       /* 8704  */
#define N_GI   (N_W + 64 * FS)         /* 13056 */
#define N_GH   (N_GI + 64 * 193)       /* 25408 */
#define N_BIG  (N_GH + 64 * 193)       /* 37760 */
#define N_BIH  (N_BIG + 64)
#define N_BHH  (N_BIH + 192)
#define N_STAT (N_BHH + 192)           /* 256 */
#define N_RED  (N_STAT + 256)          /* 512 */
#define NODE_FLOATS (N_RED + 512)
#define NODE_SMEM (NODE_FLOATS * 4)    /* ~156 KB */

__global__ __launch_bounds__(256, 1) void node_mma_kernel(
    float* __restrict__ out,
    const float* __restrict__ Wih, const float* __restrict__ Whh,
    const float* __restrict__ bih, const float* __restrict__ bhh,
    const float* __restrict__ Wig, const float* __restrict__ big,
    int t, int N)
{
    extern __shared__ float sm[];
    float*    sHx  = sm + N_HX;     // fp32 [node][k], stride 68
    float*    sInp = sm + N_INP;    // fp32 [node][k], stride 68
    uint32_t* uW   = (uint32_t*)(sm + N_W);  // tf32 chunk [n][k], stride 68
    float*    sGI  = sm + N_GI;     // [node][192], stride 193
    float*    sGH  = sm + N_GH;
    float*    sBig = sm + N_BIG;
    float*    sBih = sm + N_BIH;
    float*    sBhh = sm + N_BHH;
    float*    sStat = sm + N_STAT;
    float*    sRed  = sm + N_RED;

    const int tx = threadIdx.x;
    const int wid = tx >> 5, lane = tx & 31;
    const int g = lane >> 2, q = lane & 3;
    const int n0 = blockIdx.x * 64;
    const int toff = t * 64;
    const int r0 = (wid & 3) * 16;
    const int nh = (wid >> 2) * 32;
    const int rA = r0 + g, rB = r0 + 8 + g;
    const int gnA = n0 + rA, gnB = n0 + rB;

    // stage hx (fp32) + Wig (tf32) + biases
    for (int idx = tx; idx < 4096; idx += 256) {
        int n = idx >> 6, k = idx & 63;
        sHx[n * FS + k] = (n0 + n < N) ? out[(size_t)(n0 + n) * 256 + toff + k] : 0.f;
        uW[n * FS + k] = f2tf32(Wig[idx]);
    }
    if (tx < 64)  sBig[tx] = big[tx];
    if (tx < 192) { sBih[tx] = bih[tx]; sBhh[tx] = bhh[tx]; }
    __syncthreads();

    float acc[4][4];

    // ---- GEMM: ig = sigmoid(hx @ Wig^T + big); inp = ig * agg * invdeg ----
    #pragma unroll
    for (int j = 0; j < 4; j++) {
        int cb = nh + 8 * j + 2 * q;
        acc[j][0] = acc[j][2] = sBig[cb];
        acc[j][1] = acc[j][3] = sBig[cb + 1];
    }
    #pragma unroll
    for (int k0 = 0; k0 < 8; k0++) {
        uint32_t a0 = f2tf32(sHx[rA * FS + 8 * k0 + q]);
        uint32_t a1 = f2tf32(sHx[rB * FS + 8 * k0 + q]);
        uint32_t a2 = f2tf32(sHx[rA * FS + 8 * k0 + q + 4]);
        uint32_t a3 = f2tf32(sHx[rB * FS + 8 * k0 + q + 4]);
        #pragma unroll
        for (int j = 0; j < 4; j++) {
            uint32_t b0 = uW[(nh + 8 * j + g) * FS + 8 * k0 + q];
            uint32_t b1 = uW[(nh + 8 * j + g) * FS + 8 * k0 + q + 4];
            mma_tf32(acc[j][0], acc[j][1], acc[j][2], acc[j][3], a0, a1, a2, a3, b0, b1);
        }
    }
    {
        float invA = (gnA < N) ? g_invdeg[gnA] : 0.f;
        float invB = (gnB < N) ? g_invdeg[gnB] : 0.f;
        #pragma unroll
        for (int j = 0; j < 4; j++) {
            int cb = nh + 8 * j + 2 * q;
            float2 aA = make_float2(0.f, 0.f), aB = make_float2(0.f, 0.f);
            if (gnA < N) aA = *(const float2*)(g_agg + (size_t)gnA * 64 + cb);
            if (gnB < N) aB = *(const float2*)(g_agg + (size_t)gnB * 64 + cb);
            sInp[rA * FS + cb]     = sigm(acc[j][0]) * aA.x * invA;
            sInp[rA * FS + cb + 1] = sigm(acc[j][1]) * aA.y * invA;
            sInp[rB * FS + cb]     = sigm(acc[j][2]) * aB.x * invB;
            sInp[rB * FS + cb + 1] = sigm(acc[j][3]) * aB.y * invB;
        }
    }
    __syncthreads();

    // ---- GI = inp @ Wih^T ; GH = hx @ Whh^T  (3 chunks each) ----
    for (int pass = 0; pass < 2; pass++) {
        const float* Wsrc = pass ? Whh : Wih;
        const float* Asrc = pass ? sHx : sInp;
        float* Gdst = pass ? sGH : sGI;
        for (int c = 0; c < 3; c++) {
            for (int idx = tx; idx < 4096; idx += 256) {
                int o = idx >> 6, k = idx & 63;
                uW[o * FS + k] = f2tf32(Wsrc[(size_t)c * 4096 + idx]);
            }
            __syncthreads();
            #pragma unroll
            for (int j = 0; j < 4; j++)
                acc[j][0] = acc[j][1] = acc[j][2] = acc[j][3] = 0.f;
            #pragma unroll
            for (int k0 = 0; k0 < 8; k0++) {
                uint32_t a0 = f2tf32(Asrc[rA * FS + 8 * k0 + q]);
                uint32_t a1 = f2tf32(Asrc[rB * FS + 8 * k0 + q]);
                uint32_t a2 = f2tf32(Asrc[rA * FS + 8 * k0 + q + 4]);
                uint32_t a3 = f2tf32(Asrc[rB * FS + 8 * k0 + q + 4]);
                #pragma unroll
                for (int j = 0; j < 4; j++) {
                    uint32_t b0 = uW[(nh + 8 * j + g) * FS + 8 * k0 + q];
                    uint32_t b1 = uW[(nh + 8 * j + g) * FS + 8 * k0 + q + 4];
                    mma_tf32(acc[j][0], acc[j][1], acc[j][2], acc[j][3], a0, a1, a2, a3, b0, b1);
                }
            }
            #pragma unroll
            for (int j = 0; j < 4; j++) {
                int cb = c * 64 + nh + 8 * j + 2 * q;
                Gdst[rA * 193 + cb]     = acc[j][0];
                Gdst[rA * 193 + cb + 1] = acc[j][1];
                Gdst[rB * 193 + cb]     = acc[j][2];
                Gdst[rB * 193 + cb + 1] = acc[j][3];
            }
            __syncthreads();
        }
    }

    // ---- instance-norm stats (per node, over 192 features) ----
    {
        int part = tx >> 6;
        int n = tx & 63;
        const float* row = (part < 2) ? (sGI + n * 193) : (sGH + n * 193);
        int off = (part & 1) * 96;
        float s = 0.f, qq = 0.f;
        #pragma unroll 4
        for (int u = 0; u < 96; u++) { float v = row[off + u]; s += v; qq += v * v; }
        sRed[part * 64 + n]       = s;
        sRed[256 + part * 64 + n] = qq;
    }
    __syncthreads();
    if (tx < 128) {
        int n = tx & 63;
        int isH = tx >> 6;
        int pb = isH * 2;
        float s = sRed[pb * 64 + n] + sRed[(pb + 1) * 64 + n];
        float qq = sRed[256 + pb * 64 + n] + sRed[256 + (pb + 1) * 64 + n];
        float mu = s * (1.f / 192.f);
        float var = qq * (1.f / 192.f) - mu * mu;
        sStat[isH * 128 + n]      = mu;
        sStat[isH * 128 + 64 + n] = rsqrtf(var + 1e-5f);
    }
    __syncthreads();

    // ---- gates + hx update ----
    {
        int h = tx & 63;
        int nb = tx >> 6;
        #pragma unroll
        for (int i = 0; i < 16; i++) {
            int n = nb * 16 + i;
            int gn = n0 + n;
            if (gn >= N) continue;
            float muI = sStat[n],       rsI = sStat[64 + n];
            float muH = sStat[128 + n], rsH = sStat[192 + n];
            const float* gi = sGI + n * 193;
            const float* gh = sGH + n * 193;
            float i_r = (gi[h]       - muI) * rsI;
            float i_i = (gi[64 + h]  - muI) * rsI;
            float i_n = (gi[128 + h] - muI) * rsI;
            float h_r = (gh[h]       - muH) * rsH;
            float h_i = (gh[64 + h]  - muH) * rsH;
            float h_n = (gh[128 + h] - muH) * rsH;
            float r  = sigm(i_r + sBih[h]      + h_r + sBhh[h]);
            float z  = sigm(i_i + sBih[64 + h] + h_i + sBhh[64 + h]);
            float ng = tanhf(i_n + sBih[128 + h] + r * (h_n + sBhh[128 + h]));
            float hxo = sHx[n * FS + h];
            out[(size_t)gn * 256 + toff + 64 + h] = ng + z * (hxo - ng);
        }
    }
}

// ---------------- launcher ----------------
extern "C" void kernel_launch(void* const* d_in, const int* in_sizes, int n_in,
                              void* d_out, int out_size)
{
    const float* hx  = (const float*)d_in[0];
    const void*  eix = d_in[1];
    const float* ef  = (const float*)d_in[2];
    const float* fW1 = (const float*)d_in[3];
    const float* fb1 = (const float*)d_in[4];
    const float* fW2 = (const float*)d_in[5];
    const float* fb2 = (const float*)d_in[6];
    const float* fW3 = (const float*)d_in[7];
    const float* fb3 = (const float*)d_in[8];
    const float* Wih = (const float*)d_in[9];
    const float* Whh = (const float*)d_in[10];
    const float* bih = (const float*)d_in[11];
    const float* bhh = (const float*)d_in[12];
    const float* Wig = (const float*)d_in[13];
    const float* big = (const float*)d_in[14];
    float* out = (float*)d_out;

    const int N = in_sizes[0] / 64;
    const int E = in_sizes[2] / 13;

    cudaFuncSetAttribute(fnet_mma_kernel, cudaFuncAttributeMaxDynamicSharedMemorySize, FNET_SMEM);
    cudaFuncSetAttribute(node_mma_kernel, cudaFuncAttributeMaxDynamicSharedMemorySize, NODE_SMEM);

    detect_kernel<<<1, 256>>>((const int*)eix);
    copy_hx_kernel<<<(N * 64 + 255) / 256, 256>>>(hx, out, N);
    zero_deg_kernel<<<(NN + 255) / 256, 256>>>();
    deg_kernel<<<(E + 255) / 256, 256>>>(eix, E);
    invdeg_kernel<<<(NN + 255) / 256, 256>>>();
    fnet_mma_kernel<<<(E + 127) / 128, 256, FNET_SMEM>>>(ef, fW1, fb1, fW2, fb2, fW3, fb3, E);

    for (int t = 0; t < 3; t++) {
        zero_agg_kernel<<<((NN * 64 / 4) + 255) / 256, 256>>>();
        scatter_kernel<<<(int)(((long long)E * 4 + 255) / 256), 256>>>(eix, out, t, E);
        node_mma_kernel<<<(N + 63) / 64, 256, NODE_SMEM>>>(out, Wih, Whh, bih, bhh, Wig, big, t, N);
    }
}

// round 5
// speedup vs baseline: 2.6568x; 1.1450x over previous
#include <cuda_runtime.h>
#include <cstdint>

#define NN 100000
#define NE 1250000
#define FS 68

// ---------------- device scratch (no allocs allowed) ----------------
__device__ __align__(16) float g_w[(size_t)NE * 64];     // per-edge weights [E][64]
__device__ __align__(16) float g_agg[(size_t)NN * 64];   // scatter accumulator [N][64]
__device__ float g_deg[NN];
__device__ float g_invdeg[NN];
__device__ int   g_idx64;                                // 1 if edge_index is int64

// pre-converted tf32 weights
__device__ uint32_t g_fw1u[1024];    // [64][16] padded
__device__ uint32_t g_fw2u[4096];
__device__ uint32_t g_fw3u[4096];
__device__ uint32_t g_wigu[4096];
__device__ uint32_t g_wihu[12288];
__device__ uint32_t g_whhu[12288];

__device__ __forceinline__ float sigm(float x) { return 1.f / (1.f + expf(-x)); }

__device__ __forceinline__ void red_add_v4(float4* addr, float4 v) {
    asm volatile("red.global.add.v4.f32 [%0], {%1, %2, %3, %4};"
                 :: "l"(addr), "f"(v.x), "f"(v.y), "f"(v.z), "f"(v.w) : "memory");
}

__device__ __forceinline__ uint32_t f2tf32(float x) {
    uint32_t u;
    asm("cvt.rna.tf32.f32 %0, %1;" : "=r"(u) : "f"(x));
    return u;
}

// D[m][n] = sum_k A[m][k] * W[n][k], m16n8k8 tf32
__device__ __forceinline__ void mma_tf32(float& c0, float& c1, float& c2, float& c3,
                                         uint32_t a0, uint32_t a1, uint32_t a2, uint32_t a3,
                                         uint32_t b0, uint32_t b1)
{
    asm volatile("mma.sync.aligned.m16n8k8.row.col.f32.tf32.tf32.f32 "
                 "{%0,%1,%2,%3}, {%4,%5,%6,%7}, {%8,%9}, {%0,%1,%2,%3};"
                 : "+f"(c0), "+f"(c1), "+f"(c2), "+f"(c3)
                 : "r"(a0), "r"(a1), "r"(a2), "r"(a3), "r"(b0), "r"(b1));
}

// ---------------- prep: convert weights to tf32 once ----------------
__global__ void prep_kernel(const float* __restrict__ fW1, const float* __restrict__ fW2,
                            const float* __restrict__ fW3, const float* __restrict__ Wig,
                            const float* __restrict__ Wih, const float* __restrict__ Whh)
{
    int i = blockIdx.x * blockDim.x + threadIdx.x;
    if (i < 1024) {
        int o = i >> 4, k = i & 15;
        g_fw1u[i] = (k < 13) ? f2tf32(fW1[o * 13 + k]) : 0u;
    }
    if (i < 4096) {
        g_fw2u[i] = f2tf32(fW2[i]);
        g_fw3u[i] = f2tf32(fW3[i]);
        g_wigu[i] = f2tf32(Wig[i]);
    }
    if (i < 12288) {
        g_wihu[i] = f2tf32(Wih[i]);
        g_whhu[i] = f2tf32(Whh[i]);
    }
}

// ---------------- dtype detection for edge_index ----------------
__global__ void detect_kernel(const int* __restrict__ p) {
    __shared__ int nz;
    if (threadIdx.x == 0) nz = 0;
    __syncthreads();
    if (p[2 * threadIdx.x + 1] != 0) atomicOr(&nz, 1);
    __syncthreads();
    if (threadIdx.x == 0) g_idx64 = (nz == 0) ? 1 : 0;
}

// ---------------- trivial kernels ----------------
__global__ void copy_hx_kernel(const float* __restrict__ hx, float* __restrict__ out, int N) {
    int idx = blockIdx.x * blockDim.x + threadIdx.x;
    if (idx < N * 64) {
        int n = idx >> 6, k = idx & 63;
        out[(size_t)n * 256 + k] = hx[idx];
    }
}

__global__ void zero_agg_kernel() {
    size_t idx = (size_t)blockIdx.x * blockDim.x + threadIdx.x;
    if (idx < (size_t)NN * 64 / 4)
        ((float4*)g_agg)[idx] = make_float4(0.f, 0.f, 0.f, 0.f);
}

__global__ void zero_deg_kernel() {
    int i = blockIdx.x * blockDim.x + threadIdx.x;
    if (i < NN) g_deg[i] = 0.f;
}

__global__ void deg_kernel(const void* __restrict__ eidx, int E) {
    int e = blockIdx.x * blockDim.x + threadIdx.x;
    if (e >= E) return;
    long long d;
    if (g_idx64) d = ((const long long*)eidx)[e];
    else         d = (long long)((const int*)eidx)[e];
    atomicAdd(&g_deg[d], 1.0f);
}

__global__ void invdeg_kernel() {
    int i = blockIdx.x * blockDim.x + threadIdx.x;
    if (i < NN) g_invdeg[i] = 1.0f / fmaxf(g_deg[i], 1.0f);
}

// ---------------- fnet via mma.sync tf32 ----------------
// Block: 512 threads (16 warps), 256 edges. Warp w owns rows 16w..16w+15, in-place layers.
#define F_X   0
#define F_W1  (256 * FS)             /* 17408 */
#define F_W2  (F_W1 + 64 * FS)       /* 21760 */
#define F_W3  (F_W2 + 64 * FS)       /* 26112 */
#define F_B   (F_W3 + 64 * FS)       /* 30464 */
#define FNET_FLOATS (F_B + 192)      /* 30656 */
#define FNET_SMEM (FNET_FLOATS * 4)  /* 122624 B */

__global__ __launch_bounds__(512, 1) void fnet_mma_kernel(
    const float* __restrict__ ef,
    const float* __restrict__ fb1, const float* __restrict__ fb2,
    const float* __restrict__ fb3, int E)
{
    extern __shared__ float sm[];
    uint32_t* uX  = (uint32_t*)(sm + F_X);
    uint32_t* uW1 = (uint32_t*)(sm + F_W1);
    uint32_t* uW2 = (uint32_t*)(sm + F_W2);
    uint32_t* uW3 = (uint32_t*)(sm + F_W3);
    float*    sB  = sm + F_B;

    const int tid = threadIdx.x;
    const int wid = tid >> 5, lane = tid & 31;
    const int g = lane >> 2, q = lane & 3;
    const int e0 = blockIdx.x * 256;
    const int r0 = wid * 16;
    const int rA = r0 + g, rB = r0 + 8 + g;

    // stage X (K padded to 16, tf32)
    for (int idx = tid; idx < 256 * 16; idx += 512) {
        int e = idx >> 4, k = idx & 15;
        float v = (k < 13 && e0 + e < E) ? ef[(size_t)(e0 + e) * 13 + k] : 0.f;
        uX[e * FS + k] = f2tf32(v);
    }
    for (int idx = tid; idx < 1024; idx += 512) {
        int o = idx >> 4, k = idx & 15;
        uW1[o * FS + k] = g_fw1u[idx];
    }
    for (int idx = tid; idx < 4096; idx += 512) {
        int o = idx >> 6, k = idx & 63;
        uW2[o * FS + k] = g_fw2u[idx];
        uW3[o * FS + k] = g_fw3u[idx];
    }
    if (tid < 64) { sB[tid] = fb1[tid]; sB[64 + tid] = fb2[tid]; sB[128 + tid] = fb3[tid]; }
    __syncthreads();

    float acc[8][4];

    // ---- layer 1 (K = 16) ----
    #pragma unroll
    for (int j = 0; j < 8; j++) {
        int cb = j * 8 + 2 * q;
        acc[j][0] = acc[j][2] = sB[cb];
        acc[j][1] = acc[j][3] = sB[cb + 1];
    }
    #pragma unroll
    for (int k0 = 0; k0 < 2; k0++) {
        uint32_t a0 = uX[rA * FS + 8 * k0 + q];
        uint32_t a1 = uX[rB * FS + 8 * k0 + q];
        uint32_t a2 = uX[rA * FS + 8 * k0 + q + 4];
        uint32_t a3 = uX[rB * FS + 8 * k0 + q + 4];
        #pragma unroll
        for (int j = 0; j < 8; j++) {
            uint32_t b0 = uW1[(8 * j + g) * FS + 8 * k0 + q];
            uint32_t b1 = uW1[(8 * j + g) * FS + 8 * k0 + q + 4];
            mma_tf32(acc[j][0], acc[j][1], acc[j][2], acc[j][3], a0, a1, a2, a3, b0, b1);
        }
    }
    #pragma unroll
    for (int j = 0; j < 8; j++) {
        int cb = j * 8 + 2 * q;
        uX[rA * FS + cb]     = f2tf32(fmaxf(acc[j][0], 0.f));
        uX[rA * FS + cb + 1] = f2tf32(fmaxf(acc[j][1], 0.f));
        uX[rB * FS + cb]     = f2tf32(fmaxf(acc[j][2], 0.f));
        uX[rB * FS + cb + 1] = f2tf32(fmaxf(acc[j][3], 0.f));
    }
    __syncwarp();

    // ---- layer 2 (K = 64, relu) ----
    #pragma unroll
    for (int j = 0; j < 8; j++) {
        int cb = j * 8 + 2 * q;
        acc[j][0] = acc[j][2] = sB[64 + cb];
        acc[j][1] = acc[j][3] = sB[64 + cb + 1];
    }
    #pragma unroll
    for (int k0 = 0; k0 < 8; k0++) {
        uint32_t a0 = uX[rA * FS + 8 * k0 + q];
        uint32_t a1 = uX[rB * FS + 8 * k0 + q];
        uint32_t a2 = uX[rA * FS + 8 * k0 + q + 4];
        uint32_t a3 = uX[rB * FS + 8 * k0 + q + 4];
        #pragma unroll
        for (int j = 0; j < 8; j++) {
            uint32_t b0 = uW2[(8 * j + g) * FS + 8 * k0 + q];
            uint32_t b1 = uW2[(8 * j + g) * FS + 8 * k0 + q + 4];
            mma_tf32(acc[j][0], acc[j][1], acc[j][2], acc[j][3], a0, a1, a2, a3, b0, b1);
        }
    }
    __syncwarp();
    #pragma unroll
    for (int j = 0; j < 8; j++) {
        int cb = j * 8 + 2 * q;
        uX[rA * FS + cb]     = f2tf32(fmaxf(acc[j][0], 0.f));
        uX[rA * FS + cb + 1] = f2tf32(fmaxf(acc[j][1], 0.f));
        uX[rB * FS + cb]     = f2tf32(fmaxf(acc[j][2], 0.f));
        uX[rB * FS + cb + 1] = f2tf32(fmaxf(acc[j][3], 0.f));
    }
    __syncwarp();

    // ---- layer 3 (K = 64, no relu, fp32 out) ----
    #pragma unroll
    for (int j = 0; j < 8; j++) {
        int cb = j * 8 + 2 * q;
        acc[j][0] = acc[j][2] = sB[128 + cb];
        acc[j][1] = acc[j][3] = sB[128 + cb + 1];
    }
    #pragma unroll
    for (int k0 = 0; k0 < 8; k0++) {
        uint32_t a0 = uX[rA * FS + 8 * k0 + q];
        uint32_t a1 = uX[rB * FS + 8 * k0 + q];
        uint32_t a2 = uX[rA * FS + 8 * k0 + q + 4];
        uint32_t a3 = uX[rB * FS + 8 * k0 + q + 4];
        #pragma unroll
        for (int j = 0; j < 8; j++) {
            uint32_t b0 = uW3[(8 * j + g) * FS + 8 * k0 + q];
            uint32_t b1 = uW3[(8 * j + g) * FS + 8 * k0 + q + 4];
            mma_tf32(acc[j][0], acc[j][1], acc[j][2], acc[j][3], a0, a1, a2, a3, b0, b1);
        }
    }
    __syncwarp();
    {
        float* sX = sm + F_X;
        #pragma unroll
        for (int j = 0; j < 8; j++) {
            int cb = j * 8 + 2 * q;
            sX[rA * FS + cb]     = acc[j][0];
            sX[rA * FS + cb + 1] = acc[j][1];
            sX[rB * FS + cb]     = acc[j][2];
            sX[rB * FS + cb + 1] = acc[j][3];
        }
    }
    __syncthreads();

    // coalesced store to g_w
    {
        float4* gw = (float4*)(g_w + (size_t)e0 * 64);
        const float* sX = sm + F_X;
        #pragma unroll
        for (int i = 0; i < 8; i++) {
            int gidx = i * 512 + tid;       // 0..4095 float4s
            int r = gidx >> 4, c4 = gidx & 15;
            if (e0 + r < E)
                gw[gidx] = *(const float4*)(sX + r * FS + c4 * 4);
        }
    }
}

// ---------------- gather-multiply-scatter (per repeat) ----------------
__global__ void scatter_kernel(const void* __restrict__ eidx,
                               const float* __restrict__ out, int t, int E)
{
    long long idx = (long long)blockIdx.x * blockDim.x + threadIdx.x;
    if (idx >= (long long)E * 4) return;
    int e = (int)(idx >> 2);
    int q = (int)(idx & 3);
    long long d, s;
    if (g_idx64) {
        const long long* p = (const long long*)eidx;
        d = p[e]; s = p[E + e];
    } else {
        const int* p = (const int*)eidx;
        d = p[e]; s = p[E + e];
    }
    const float4* hv = (const float4*)(out + s * 256 + t * 64);
    const float4* wv = (const float4*)(g_w + (size_t)e * 64);
    float4*       av = (float4*)(g_agg + d * 64);
    #pragma unroll
    for (int j = 0; j < 4; j++) {
        int c = j * 4 + q;
        float4 h = __ldg(hv + c);
        float4 w = __ldg(wv + c);
        float4 m = make_float4(h.x * w.x, h.y * w.y, h.z * w.z, h.w * w.w);
        red_add_v4(av + c, m);
    }
}

// ---------------- fused GRU node update: regs-resident GI/GH ----------------
// Block: 512 threads (16 warps), 64 nodes.
// warp: rowgrp = wid&3 (16 rows), quarter = wid>>2 (16 cols).
#define N_UHX  0                      /* tf32 hx [n][k] stride 68 : 4352 */
#define N_HX32 (N_UHX + 64 * FS)      /* fp32 hx : 4352 */
#define N_UINP (N_HX32 + 64 * FS)     /* tf32 inp / fp32 out stage : 4352 */
#define N_W    (N_UINP + 64 * FS)     /* weight stage: Wih_c @0, Whh_c @4352 : 8704 */
#define N_BIG  (N_W + 2 * 64 * FS)    /* 64 */
#define N_BIH  (N_BIG + 64)           /* 192 */
#define N_BHH  (N_BIH + 192)          /* 192 */
#define N_RED  (N_BHH + 192)          /* 4*64*4 = 1024 */
#define N_STAT (N_RED + 1024)         /* 64*4 = 256 */
#define NODE_FLOATS (N_STAT + 256)
#define NODE_SMEM (NODE_FLOATS * 4)   /* ~94 KB */

__global__ __launch_bounds__(512, 1) void node_mma_kernel(
    float* __restrict__ out,
    const float* __restrict__ bih, const float* __restrict__ bhh,
    const float* __restrict__ big, int t, int N)
{
    extern __shared__ float sm[];
    uint32_t* uHx   = (uint32_t*)(sm + N_UHX);
    float*    sHx32 = sm + N_HX32;
    uint32_t* uInp  = (uint32_t*)(sm + N_UINP);
    float*    sOut  = sm + N_UINP;           // reused after GEMMs
    uint32_t* uW    = (uint32_t*)(sm + N_W); // [o][k] stride 68, Wih chunk; +4352 Whh chunk
    float*    sBig  = sm + N_BIG;
    float*    sBih  = sm + N_BIH;
    float*    sBhh  = sm + N_BHH;
    float*    sRed  = sm + N_RED;            // [quarter][row][4]
    float*    sStat = sm + N_STAT;           // [row][muI, rsI, muH, rsH]

    const int tx = threadIdx.x;
    const int wid = tx >> 5, lane = tx & 31;
    const int g = lane >> 2, q = lane & 3;
    const int rowgrp = wid & 3, qt = wid >> 2;
    const int nq = qt * 16;
    const int n0 = blockIdx.x * 64;
    const int toff = t * 64;
    const int rA = rowgrp * 16 + g, rB = rA + 8;
    const int gnA = n0 + rA, gnB = n0 + rB;

    // ---- stage hx (both fp32 and tf32) + Wig into weight buffer + biases ----
    for (int idx = tx; idx < 4096; idx += 512) {
        int n = idx >> 6, k = idx & 63;
        float v = (n0 + n < N) ? out[(size_t)(n0 + n) * 256 + toff + k] : 0.f;
        sHx32[n * FS + k] = v;
        uHx[n * FS + k] = f2tf32(v);
        uW[(idx >> 6) * FS + (idx & 63)] = g_wigu[idx];
    }
    if (tx < 64)  sBig[tx] = big[tx];
    if (tx < 192) { sBih[tx] = bih[tx]; sBhh[tx] = bhh[tx]; }
    __syncthreads();

    // ---- inp = sigmoid(hx @ Wig^T + big) * agg * invdeg ; zero agg ----
    {
        float aw[2][4];
        #pragma unroll
        for (int j = 0; j < 2; j++) {
            int cb = nq + 8 * j + 2 * q;
            aw[j][0] = aw[j][2] = sBig[cb];
            aw[j][1] = aw[j][3] = sBig[cb + 1];
        }
        #pragma unroll
        for (int k0 = 0; k0 < 8; k0++) {
            uint32_t a0 = uHx[rA * FS + 8 * k0 + q];
            uint32_t a1 = uHx[rB * FS + 8 * k0 + q];
            uint32_t a2 = uHx[rA * FS + 8 * k0 + q + 4];
            uint32_t a3 = uHx[rB * FS + 8 * k0 + q + 4];
            #pragma unroll
            for (int j = 0; j < 2; j++) {
                uint32_t b0 = uW[(nq + 8 * j + g) * FS + 8 * k0 + q];
                uint32_t b1 = uW[(nq + 8 * j + g) * FS + 8 * k0 + q + 4];
                mma_tf32(aw[j][0], aw[j][1], aw[j][2], aw[j][3], a0, a1, a2, a3, b0, b1);
            }
        }
        float invA = (gnA < N) ? g_invdeg[gnA] : 0.f;
        float invB = (gnB < N) ? g_invdeg[gnB] : 0.f;
        #pragma unroll
        for (int j = 0; j < 2; j++) {
            int cb = nq + 8 * j + 2 * q;
            float2 aA = make_float2(0.f, 0.f), aB = make_float2(0.f, 0.f);
            if (gnA < N) {
                aA = *(float2*)(g_agg + (size_t)gnA * 64 + cb);
                *(float2*)(g_agg + (size_t)gnA * 64 + cb) = make_float2(0.f, 0.f);
            }
            if (gnB < N) {
                aB = *(float2*)(g_agg + (size_t)gnB * 64 + cb);
                *(float2*)(g_agg + (size_t)gnB * 64 + cb) = make_float2(0.f, 0.f);
            }
            uInp[rA * FS + cb]     = f2tf32(sigm(aw[j][0]) * aA.x * invA);
            uInp[rA * FS + cb + 1] = f2tf32(sigm(aw[j][1]) * aA.y * invA);
            uInp[rB * FS + cb]     = f2tf32(sigm(aw[j][2]) * aB.x * invB);
            uInp[rB * FS + cb + 1] = f2tf32(sigm(aw[j][3]) * aB.y * invB);
        }
    }
    __syncthreads();

    // ---- GI = inp @ Wih^T ; GH = hx @ Whh^T : accumulators in registers ----
    float accI[3][2][4], accH[3][2][4];
    for (int c = 0; c < 3; c++) {
        for (int idx = tx; idx < 4096; idx += 512) {
            int o = idx >> 6, k = idx & 63;
            uW[o * FS + k]        = g_wihu[c * 4096 + idx];
            uW[4352 + o * FS + k] = g_whhu[c * 4096 + idx];
        }
        __syncthreads();
        #pragma unroll
        for (int j = 0; j < 2; j++)
            #pragma unroll
            for (int v = 0; v < 4; v++) { accI[c][j][v] = 0.f; accH[c][j][v] = 0.f; }
        #pragma unroll
        for (int k0 = 0; k0 < 8; k0++) {
            uint32_t aI0 = uInp[rA * FS + 8 * k0 + q];
            uint32_t aI1 = uInp[rB * FS + 8 * k0 + q];
            uint32_t aI2 = uInp[rA * FS + 8 * k0 + q + 4];
            uint32_t aI3 = uInp[rB * FS + 8 * k0 + q + 4];
            uint32_t aH0 = uHx[rA * FS + 8 * k0 + q];
            uint32_t aH1 = uHx[rB * FS + 8 * k0 + q];
            uint32_t aH2 = uHx[rA * FS + 8 * k0 + q + 4];
            uint32_t aH3 = uHx[rB * FS + 8 * k0 + q + 4];
            #pragma unroll
            for (int j = 0; j < 2; j++) {
                int brow = (nq + 8 * j + g) * FS + 8 * k0 + q;
                uint32_t b0 = uW[brow], b1 = uW[brow + 4];
                mma_tf32(accI[c][j][0], accI[c][j][1], accI[c][j][2], accI[c][j][3],
                         aI0, aI1, aI2, aI3, b0, b1);
                uint32_t c0 = uW[4352 + brow], c1 = uW[4352 + brow + 4];
                mma_tf32(accH[c][j][0], accH[c][j][1], accH[c][j][2], accH[c][j][3],
                         aH0, aH1, aH2, aH3, c0, c1);
            }
        }
        __syncthreads();
    }

    // ---- instance-norm stats: quad shfl + cross-quarter smem reduce ----
    {
        float sIA = 0.f, qIA = 0.f, sIB = 0.f, qIB = 0.f;
        float sHA = 0.f, qHA = 0.f, sHB = 0.f, qHB = 0.f;
        #pragma unroll
        for (int c = 0; c < 3; c++)
            #pragma unroll
            for (int j = 0; j < 2; j++) {
                float a0 = accI[c][j][0], a1 = accI[c][j][1];
                float a2 = accI[c][j][2], a3 = accI[c][j][3];
                sIA += a0 + a1; qIA += a0 * a0 + a1 * a1;
                sIB += a2 + a3; qIB += a2 * a2 + a3 * a3;
                float h0 = accH[c][j][0], h1 = accH[c][j][1];
                float h2 = accH[c][j][2], h3 = accH[c][j][3];
                sHA += h0 + h1; qHA += h0 * h0 + h1 * h1;
                sHB += h2 + h3; qHB += h2 * h2 + h3 * h3;
            }
        #pragma unroll
        for (int m = 1; m <= 2; m <<= 1) {
            sIA += __shfl_xor_sync(0xffffffffu, sIA, m);
            qIA += __shfl_xor_sync(0xffffffffu, qIA, m);
            sIB += __shfl_xor_sync(0xffffffffu, sIB, m);
            qIB += __shfl_xor_sync(0xffffffffu, qIB, m);
            sHA += __shfl_xor_sync(0xffffffffu, sHA, m);
            qHA += __shfl_xor_sync(0xffffffffu, qHA, m);
            sHB += __shfl_xor_sync(0xffffffffu, sHB, m);
            qHB += __shfl_xor_sync(0xffffffffu, qHB, m);
        }
        if (q == 0) {
            float* rdA = sRed + (qt * 64 + rA) * 4;
            rdA[0] = sIA; rdA[1] = qIA; rdA[2] = sHA; rdA[3] = qHA;
            float* rdB = sRed + (qt * 64 + rB) * 4;
            rdB[0] = sIB; rdB[1] = qIB; rdB[2] = sHB; rdB[3] = qHB;
        }
    }
    __syncthreads();
    if (tx < 64) {
        float sI = 0.f, qI = 0.f, sH = 0.f, qH = 0.f;
        #pragma unroll
        for (int qt2 = 0; qt2 < 4; qt2++) {
            const float* rd = sRed + (qt2 * 64 + tx) * 4;
            sI += rd[0]; qI += rd[1]; sH += rd[2]; qH += rd[3];
        }
        float muI = sI * (1.f / 192.f);
        float varI = qI * (1.f / 192.f) - muI * muI;
        float muH = sH * (1.f / 192.f);
        float varH = qH * (1.f / 192.f) - muH * muH;
        sStat[tx * 4 + 0] = muI;
        sStat[tx * 4 + 1] = rsqrtf(varI + 1e-5f);
        sStat[tx * 4 + 2] = muH;
        sStat[tx * 4 + 3] = rsqrtf(varH + 1e-5f);
    }
    __syncthreads();

    // ---- gates straight from registers, stage result ----
    {
        float muIA = sStat[rA * 4 + 0], rsIA = sStat[rA * 4 + 1];
        float muHA = sStat[rA * 4 + 2], rsHA = sStat[rA * 4 + 3];
        float muIB = sStat[rB * 4 + 0], rsIB = sStat[rB * 4 + 1];
        float muHB = sStat[rB * 4 + 2], rsHB = sStat[rB * 4 + 3];
        #pragma unroll
        for (int j = 0; j < 2; j++) {
            #pragma unroll
            for (int v = 0; v < 2; v++) {
                int cb = nq + 8 * j + 2 * q + v;
                float b_r = sBih[cb],       c_r = sBhh[cb];
                float b_i = sBih[64 + cb],  c_i = sBhh[64 + cb];
                float b_n = sBih[128 + cb], c_n = sBhh[128 + cb];
                // row A
                {
                    float i_r = (accI[0][j][v] - muIA) * rsIA;
                    float i_i = (accI[1][j][v] - muIA) * rsIA;
                    float i_n = (accI[2][j][v] - muIA) * rsIA;
                    float h_r = (accH[0][j][v] - muHA) * rsHA;
                    float h_i = (accH[1][j][v] - muHA) * rsHA;
                    float h_n = (accH[2][j][v] - muHA) * rsHA;
                    float r  = sigm(i_r + b_r + h_r + c_r);
                    float z  = sigm(i_i + b_i + h_i + c_i);
                    float ng = tanhf(i_n + b_n + r * (h_n + c_n));
                    float hxo = sHx32[rA * FS + cb];
                    sOut[rA * FS + cb] = ng + z * (hxo - ng);
                }
                // row B
                {
                    float i_r = (accI[0][j][v + 2] - muIB) * rsIB;
                    float i_i = (accI[1][j][v + 2] - muIB) * rsIB;
                    float i_n = (accI[2][j][v + 2] - muIB) * rsIB;
                    float h_r = (accH[0][j][v + 2] - muHB) * rsHB;
                    float h_i = (accH[1][j][v + 2] - muHB) * rsHB;
                    float h_n = (accH[2][j][v + 2] - muHB) * rsHB;
                    float r  = sigm(i_r + b_r + h_r + c_r);
                    float z  = sigm(i_i + b_i + h_i + c_i);
                    float ng = tanhf(i_n + b_n + r * (h_n + c_n));
                    float hxo = sHx32[rB * FS + cb];
                    sOut[rB * FS + cb] = ng + z * (hxo - ng);
                }
            }
        }
    }
    __syncthreads();

    // ---- coalesced write of new hx ----
    for (int idx = tx; idx < 4096; idx += 512) {
        int n = idx >> 6, k = idx & 63;
        if (n0 + n < N)
            out[(size_t)(n0 + n) * 256 + toff + 64 + k] = sOut[n * FS + k];
    }
}

// ---------------- launcher ----------------
extern "C" void kernel_launch(void* const* d_in, const int* in_sizes, int n_in,
                              void* d_out, int out_size)
{
    const float* hx  = (const float*)d_in[0];
    const void*  eix = d_in[1];
    const float* ef  = (const float*)d_in[2];
    const float* fW1 = (const float*)d_in[3];
    const float* fb1 = (const float*)d_in[4];
    const float* fW2 = (const float*)d_in[5];
    const float* fb2 = (const float*)d_in[6];
    const float* fW3 = (const float*)d_in[7];
    const float* fb3 = (const float*)d_in[8];
    const float* Wih = (const float*)d_in[9];
    const float* Whh = (const float*)d_in[10];
    const float* bih = (const float*)d_in[11];
    const float* bhh = (const float*)d_in[12];
    const float* Wig = (const float*)d_in[13];
    const float* big = (const float*)d_in[14];
    float* out = (float*)d_out;

    const int N = in_sizes[0] / 64;
    const int E = in_sizes[2] / 13;

    cudaFuncSetAttribute(fnet_mma_kernel, cudaFuncAttributeMaxDynamicSharedMemorySize, FNET_SMEM);
    cudaFuncSetAttribute(node_mma_kernel, cudaFuncAttributeMaxDynamicSharedMemorySize, NODE_SMEM);

    detect_kernel<<<1, 256>>>((const int*)eix);
    prep_kernel<<<(12288 + 255) / 256, 256>>>(fW1, fW2, fW3, Wig, Wih, Whh);
    copy_hx_kernel<<<(N * 64 + 255) / 256, 256>>>(hx, out, N);
    zero_deg_kernel<<<(NN + 255) / 256, 256>>>();
    deg_kernel<<<(E + 255) / 256, 256>>>(eix, E);
    invdeg_kernel<<<(NN + 255) / 256, 256>>>();
    zero_agg_kernel<<<((NN * 64 / 4) + 255) / 256, 256>>>();
    fnet_mma_kernel<<<(E + 255) / 256, 512, FNET_SMEM>>>(ef, fb1, fb2, fb3, E);

    for (int t = 0; t < 3; t++) {
        scatter_kernel<<<(int)(((long long)E * 4 + 255) / 256), 256>>>(eix, out, t, E);
        node_mma_kernel<<<(N + 63) / 64, 512, NODE_SMEM>>>(out, bih, bhh, big, t, N);
    }
}

// round 6
// speedup vs baseline: 2.7587x; 1.0384x over previous
#include <cuda_runtime.h>
#include <cstdint>

#define NN 100000
#define NE 1250000
#define FS 68

// ---------------- device scratch (no allocs allowed) ----------------
__device__ __align__(16) float g_wp[(size_t)NE * 64];    // per-edge weights, BINNED by dst
__device__ int g_srcp[NE];                               // src node per binned position
__device__ int g_invperm[NE];                            // edge -> binned position
__device__ int g_degi[NN];
__device__ int g_start[NN];
__device__ int g_cursor[NN];
__device__ int g_bsum[128];
__device__ int g_boff[128];
__device__ int g_idx64;

// pre-converted tf32 weights
__device__ uint32_t g_fw1u[1024];    // [64][16] padded
__device__ uint32_t g_fw2u[4096];
__device__ uint32_t g_fw3u[4096];
__device__ uint32_t g_wigu[4096];
__device__ uint32_t g_wihu[12288];
__device__ uint32_t g_whhu[12288];

__device__ __forceinline__ float sigm(float x) { return 1.f / (1.f + expf(-x)); }

__device__ __forceinline__ uint32_t f2tf32(float x) {
    uint32_t u;
    asm("cvt.rna.tf32.f32 %0, %1;" : "=r"(u) : "f"(x));
    return u;
}

// D[m][n] = sum_k A[m][k] * W[n][k], m16n8k8 tf32
__device__ __forceinline__ void mma_tf32(float& c0, float& c1, float& c2, float& c3,
                                         uint32_t a0, uint32_t a1, uint32_t a2, uint32_t a3,
                                         uint32_t b0, uint32_t b1)
{
    asm volatile("mma.sync.aligned.m16n8k8.row.col.f32.tf32.tf32.f32 "
                 "{%0,%1,%2,%3}, {%4,%5,%6,%7}, {%8,%9}, {%0,%1,%2,%3};"
                 : "+f"(c0), "+f"(c1), "+f"(c2), "+f"(c3)
                 : "r"(a0), "r"(a1), "r"(a2), "r"(a3), "r"(b0), "r"(b1));
}

// ---------------- prep: convert weights to tf32 once ----------------
__global__ void prep_kernel(const float* __restrict__ fW1, const float* __restrict__ fW2,
                            const float* __restrict__ fW3, const float* __restrict__ Wig,
                            const float* __restrict__ Wih, const float* __restrict__ Whh)
{
    int i = blockIdx.x * blockDim.x + threadIdx.x;
    if (i < 1024) {
        int o = i >> 4, k = i & 15;
        g_fw1u[i] = (k < 13) ? f2tf32(fW1[o * 13 + k]) : 0u;
    }
    if (i < 4096) {
        g_fw2u[i] = f2tf32(fW2[i]);
        g_fw3u[i] = f2tf32(fW3[i]);
        g_wigu[i] = f2tf32(Wig[i]);
    }
    if (i < 12288) {
        g_wihu[i] = f2tf32(Wih[i]);
        g_whhu[i] = f2tf32(Whh[i]);
    }
}

// ---------------- dtype detection for edge_index ----------------
__global__ void detect_kernel(const int* __restrict__ p) {
    __shared__ int nz;
    if (threadIdx.x == 0) nz = 0;
    __syncthreads();
    if (p[2 * threadIdx.x + 1] != 0) atomicOr(&nz, 1);
    __syncthreads();
    if (threadIdx.x == 0) g_idx64 = (nz == 0) ? 1 : 0;
}

// ---------------- CSR build ----------------
__global__ void copy_hx_kernel(const float* __restrict__ hx, float* __restrict__ out, int N) {
    int idx = blockIdx.x * blockDim.x + threadIdx.x;
    if (idx < N * 64) {
        int n = idx >> 6, k = idx & 63;
        out[(size_t)n * 256 + k] = hx[idx];
    }
}

__global__ void zero_cnt_kernel(int N) {
    int i = blockIdx.x * blockDim.x + threadIdx.x;
    if (i < N) { g_degi[i] = 0; g_cursor[i] = 0; }
}

__global__ void degi_kernel(const void* __restrict__ eidx, int E) {
    int e = blockIdx.x * blockDim.x + threadIdx.x;
    if (e >= E) return;
    int d;
    if (g_idx64) d = (int)((const long long*)eidx)[e];
    else         d = ((const int*)eidx)[e];
    atomicAdd(&g_degi[d], 1);
}

// per-1024-element block scan
__global__ void scan1_kernel(int N) {
    __shared__ int sS[256];
    int b = blockIdx.x, tid = threadIdx.x;
    int base = b * 1024 + tid * 4;
    int v0 = (base + 0 < N) ? g_degi[base + 0] : 0;
    int v1 = (base + 1 < N) ? g_degi[base + 1] : 0;
    int v2 = (base + 2 < N) ? g_degi[base + 2] : 0;
    int v3 = (base + 3 < N) ? g_degi[base + 3] : 0;
    int tsum = v0 + v1 + v2 + v3;
    sS[tid] = tsum;
    __syncthreads();
    for (int off = 1; off < 256; off <<= 1) {
        int x = (tid >= off) ? sS[tid - off] : 0;
        __syncthreads();
        sS[tid] += x;
        __syncthreads();
    }
    int excl = sS[tid] - tsum;
    if (base + 0 < N) g_start[base + 0] = excl;
    if (base + 1 < N) g_start[base + 1] = excl + v0;
    if (base + 2 < N) g_start[base + 2] = excl + v0 + v1;
    if (base + 3 < N) g_start[base + 3] = excl + v0 + v1 + v2;
    if (tid == 255) g_bsum[b] = sS[255];
}

__global__ void scan2_kernel(int nb) {
    if (threadIdx.x == 0) {
        int acc = 0;
        for (int i = 0; i < nb; i++) { int t = g_bsum[i]; g_boff[i] = acc; acc += t; }
    }
}

__global__ void scan3_kernel(int N) {
    int i = blockIdx.x * 256 + threadIdx.x;
    if (i < N) g_start[i] += g_boff[i >> 10];
}

__global__ void bin_kernel(const void* __restrict__ eidx, int E) {
    int e = blockIdx.x * blockDim.x + threadIdx.x;
    if (e >= E) return;
    int d, s;
    if (g_idx64) {
        const long long* p = (const long long*)eidx;
        d = (int)p[e]; s = (int)p[E + e];
    } else {
        const int* p = (const int*)eidx;
        d = p[e]; s = p[E + e];
    }
    int pos = g_start[d] + atomicAdd(&g_cursor[d], 1);
    g_invperm[e] = pos;
    g_srcp[pos] = s;
}

// ---------------- fnet via mma.sync tf32, writes binned rows ----------------
// Block: 512 threads (16 warps), 256 edges, in-place layers per warp.
#define F_X   0
#define F_W1  (256 * FS)             /* 17408 */
#define F_W2  (F_W1 + 64 * FS)       /* 21760 */
#define F_W3  (F_W2 + 64 * FS)       /* 26112 */
#define F_B   (F_W3 + 64 * FS)       /* 30464 */
#define F_P   (F_B + 192)            /* 30656: perm, 256 ints */
#define FNET_FLOATS (F_P + 256)
#define FNET_SMEM (FNET_FLOATS * 4)

__global__ __launch_bounds__(512, 1) void fnet_mma_kernel(
    const float* __restrict__ ef,
    const float* __restrict__ fb1, const float* __restrict__ fb2,
    const float* __restrict__ fb3, int E)
{
    extern __shared__ float sm[];
    uint32_t* uX  = (uint32_t*)(sm + F_X);
    uint32_t* uW1 = (uint32_t*)(sm + F_W1);
    uint32_t* uW2 = (uint32_t*)(sm + F_W2);
    uint32_t* uW3 = (uint32_t*)(sm + F_W3);
    float*    sB  = sm + F_B;
    int*      sP  = (int*)(sm + F_P);

    const int tid = threadIdx.x;
    const int wid = tid >> 5, lane = tid & 31;
    const int g = lane >> 2, q = lane & 3;
    const int e0 = blockIdx.x * 256;
    const int r0 = wid * 16;
    const int rA = r0 + g, rB = r0 + 8 + g;

    // stage X (K padded to 16, tf32) + perm
    for (int idx = tid; idx < 256 * 16; idx += 512) {
        int e = idx >> 4, k = idx & 15;
        float v = (k < 13 && e0 + e < E) ? ef[(size_t)(e0 + e) * 13 + k] : 0.f;
        uX[e * FS + k] = f2tf32(v);
    }
    if (tid < 256) sP[tid] = (e0 + tid < E) ? g_invperm[e0 + tid] : -1;
    for (int idx = tid; idx < 1024; idx += 512) {
        int o = idx >> 4, k = idx & 15;
        uW1[o * FS + k] = g_fw1u[idx];
    }
    for (int idx = tid; idx < 4096; idx += 512) {
        int o = idx >> 6, k = idx & 63;
        uW2[o * FS + k] = g_fw2u[idx];
        uW3[o * FS + k] = g_fw3u[idx];
    }
    if (tid < 64) { sB[tid] = fb1[tid]; sB[64 + tid] = fb2[tid]; sB[128 + tid] = fb3[tid]; }
    __syncthreads();

    float acc[8][4];

    // ---- layer 1 (K = 16) ----
    #pragma unroll
    for (int j = 0; j < 8; j++) {
        int cb = j * 8 + 2 * q;
        acc[j][0] = acc[j][2] = sB[cb];
        acc[j][1] = acc[j][3] = sB[cb + 1];
    }
    #pragma unroll
    for (int k0 = 0; k0 < 2; k0++) {
        uint32_t a0 = uX[rA * FS + 8 * k0 + q];
        uint32_t a1 = uX[rB * FS + 8 * k0 + q];
        uint32_t a2 = uX[rA * FS + 8 * k0 + q + 4];
        uint32_t a3 = uX[rB * FS + 8 * k0 + q + 4];
        #pragma unroll
        for (int j = 0; j < 8; j++) {
            uint32_t b0 = uW1[(8 * j + g) * FS + 8 * k0 + q];
            uint32_t b1 = uW1[(8 * j + g) * FS + 8 * k0 + q + 4];
            mma_tf32(acc[j][0], acc[j][1], acc[j][2], acc[j][3], a0, a1, a2, a3, b0, b1);
        }
    }
    #pragma unroll
    for (int j = 0; j < 8; j++) {
        int cb = j * 8 + 2 * q;
        uX[rA * FS + cb]     = f2tf32(fmaxf(acc[j][0], 0.f));
        uX[rA * FS + cb + 1] = f2tf32(fmaxf(acc[j][1], 0.f));
        uX[rB * FS + cb]     = f2tf32(fmaxf(acc[j][2], 0.f));
        uX[rB * FS + cb + 1] = f2tf32(fmaxf(acc[j][3], 0.f));
    }
    __syncwarp();

    // ---- layer 2 (K = 64, relu) ----
    #pragma unroll
    for (int j = 0; j < 8; j++) {
        int cb = j * 8 + 2 * q;
        acc[j][0] = acc[j][2] = sB[64 + cb];
        acc[j][1] = acc[j][3] = sB[64 + cb + 1];
    }
    #pragma unroll
    for (int k0 = 0; k0 < 8; k0++) {
        uint32_t a0 = uX[rA * FS + 8 * k0 + q];
        uint32_t a1 = uX[rB * FS + 8 * k0 + q];
        uint32_t a2 = uX[rA * FS + 8 * k0 + q + 4];
        uint32_t a3 = uX[rB * FS + 8 * k0 + q + 4];
        #pragma unroll
        for (int j = 0; j < 8; j++) {
            uint32_t b0 = uW2[(8 * j + g) * FS + 8 * k0 + q];
            uint32_t b1 = uW2[(8 * j + g) * FS + 8 * k0 + q + 4];
            mma_tf32(acc[j][0], acc[j][1], acc[j][2], acc[j][3], a0, a1, a2, a3, b0, b1);
        }
    }
    __syncwarp();
    #pragma unroll
    for (int j = 0; j < 8; j++) {
        int cb = j * 8 + 2 * q;
        uX[rA * FS + cb]     = f2tf32(fmaxf(acc[j][0], 0.f));
        uX[rA * FS + cb + 1] = f2tf32(fmaxf(acc[j][1], 0.f));
        uX[rB * FS + cb]     = f2tf32(fmaxf(acc[j][2], 0.f));
        uX[rB * FS + cb + 1] = f2tf32(fmaxf(acc[j][3], 0.f));
    }
    __syncwarp();

    // ---- layer 3 (K = 64, no relu, fp32 out) ----
    #pragma unroll
    for (int j = 0; j < 8; j++) {
        int cb = j * 8 + 2 * q;
        acc[j][0] = acc[j][2] = sB[128 + cb];
        acc[j][1] = acc[j][3] = sB[128 + cb + 1];
    }
    #pragma unroll
    for (int k0 = 0; k0 < 8; k0++) {
        uint32_t a0 = uX[rA * FS + 8 * k0 + q];
        uint32_t a1 = uX[rB * FS + 8 * k0 + q];
        uint32_t a2 = uX[rA * FS + 8 * k0 + q + 4];
        uint32_t a3 = uX[rB * FS + 8 * k0 + q + 4];
        #pragma unroll
        for (int j = 0; j < 8; j++) {
            uint32_t b0 = uW3[(8 * j + g) * FS + 8 * k0 + q];
            uint32_t b1 = uW3[(8 * j + g) * FS + 8 * k0 + q + 4];
            mma_tf32(acc[j][0], acc[j][1], acc[j][2], acc[j][3], a0, a1, a2, a3, b0, b1);
        }
    }
    __syncwarp();
    {
        float* sX = sm + F_X;
        #pragma unroll
        for (int j = 0; j < 8; j++) {
            int cb = j * 8 + 2 * q;
            sX[rA * FS + cb]     = acc[j][0];
            sX[rA * FS + cb + 1] = acc[j][1];
            sX[rB * FS + cb]     = acc[j][2];
            sX[rB * FS + cb + 1] = acc[j][3];
        }
    }
    __syncthreads();

    // store rows to their BINNED positions in g_wp
    {
        const float* sX = sm + F_X;
        #pragma unroll
        for (int i = 0; i < 8; i++) {
            int gidx = i * 512 + tid;       // 0..4095 float4s
            int r = gidx >> 4, c4 = gidx & 15;
            int dst = sP[r];
            if (dst >= 0)
                ((float4*)g_wp)[(size_t)dst * 16 + c4] = *(const float4*)(sX + r * FS + c4 * 4);
        }
    }
}

// ---------------- fused agg + GRU node update ----------------
// Block: 512 threads (16 warps), 64 nodes.
#define N_UHX  0
#define N_HX32 (N_UHX + 64 * FS)
#define N_UINP (N_HX32 + 64 * FS)
#define N_W    (N_UINP + 64 * FS)
#define N_AGG  (N_W + 2 * 64 * FS)
#define N_BIG  (N_AGG + 64 * FS)
#define N_BIH  (N_BIG + 64)
#define N_BHH  (N_BIH + 192)
#define N_RED  (N_BHH + 192)
#define N_STAT (N_RED + 1024)
#define NODE_FLOATS (N_STAT + 256)
#define NODE_SMEM (NODE_FLOATS * 4)   /* ~111 KB */

__global__ __launch_bounds__(512, 1) void node_mma_kernel(
    float* __restrict__ out,
    const float* __restrict__ bih, const float* __restrict__ bhh,
    const float* __restrict__ big, int t, int N)
{
    extern __shared__ float sm[];
    uint32_t* uHx   = (uint32_t*)(sm + N_UHX);
    float*    sHx32 = sm + N_HX32;
    uint32_t* uInp  = (uint32_t*)(sm + N_UINP);
    float*    sOut  = sm + N_UINP;
    uint32_t* uW    = (uint32_t*)(sm + N_W);
    float*    sAgg  = sm + N_AGG;
    float*    sBig  = sm + N_BIG;
    float*    sBih  = sm + N_BIH;
    float*    sBhh  = sm + N_BHH;
    float*    sRed  = sm + N_RED;
    float*    sStat = sm + N_STAT;

    const int tx = threadIdx.x;
    const int wid = tx >> 5, lane = tx & 31;
    const int g = lane >> 2, q = lane & 3;
    const int rowgrp = wid & 3, qt = wid >> 2;
    const int nq = qt * 16;
    const int n0 = blockIdx.x * 64;
    const int toff = t * 64;
    const int rA = rowgrp * 16 + g, rB = rA + 8;
    const int gnA = n0 + rA, gnB = n0 + rB;

    // ---- stage hx + Wig + biases ----
    for (int idx = tx; idx < 4096; idx += 512) {
        int n = idx >> 6, k = idx & 63;
        float v = (n0 + n < N) ? out[(size_t)(n0 + n) * 256 + toff + k] : 0.f;
        sHx32[n * FS + k] = v;
        uHx[n * FS + k] = f2tf32(v);
        uW[(idx >> 6) * FS + (idx & 63)] = g_wigu[idx];
    }
    if (tx < 64)  sBig[tx] = big[tx];
    if (tx < 192) { sBih[tx] = bih[tx]; sBhh[tx] = bhh[tx]; }

    // ---- in-block aggregation: warp wid owns nodes wid*4 .. wid*4+3 ----
    {
        const float* o_t = out + toff;
        #pragma unroll
        for (int u = 0; u < 4; u++) {
            int ln = wid * 4 + u;
            int gn = n0 + ln;
            float ax = 0.f, ay = 0.f, bx = 0.f, by = 0.f;
            if (gn < N) {
                int start = g_start[gn];
                int deg   = g_degi[gn];
                int i = 0;
                for (; i + 2 <= deg; i += 2) {
                    int p0 = start + i, p1 = start + i + 1;
                    int s0 = g_srcp[p0], s1 = g_srcp[p1];
                    float2 w0 = *(const float2*)(g_wp + (size_t)p0 * 64 + 2 * lane);
                    float2 h0 = *(const float2*)(o_t + (size_t)s0 * 256 + 2 * lane);
                    float2 w1 = *(const float2*)(g_wp + (size_t)p1 * 64 + 2 * lane);
                    float2 h1 = *(const float2*)(o_t + (size_t)s1 * 256 + 2 * lane);
                    ax += w0.x * h0.x; ay += w0.y * h0.y;
                    bx += w1.x * h1.x; by += w1.y * h1.y;
                }
                if (i < deg) {
                    int p0 = start + i;
                    int s0 = g_srcp[p0];
                    float2 w0 = *(const float2*)(g_wp + (size_t)p0 * 64 + 2 * lane);
                    float2 h0 = *(const float2*)(o_t + (size_t)s0 * 256 + 2 * lane);
                    ax += w0.x * h0.x; ay += w0.y * h0.y;
                }
            }
            sAgg[ln * FS + 2 * lane]     = ax + bx;
            sAgg[ln * FS + 2 * lane + 1] = ay + by;
        }
    }
    __syncthreads();

    // ---- inp = sigmoid(hx @ Wig^T + big) * agg * invdeg ----
    {
        float aw[2][4];
        #pragma unroll
        for (int j = 0; j < 2; j++) {
            int cb = nq + 8 * j + 2 * q;
            aw[j][0] = aw[j][2] = sBig[cb];
            aw[j][1] = aw[j][3] = sBig[cb + 1];
        }
        #pragma unroll
        for (int k0 = 0; k0 < 8; k0++) {
            uint32_t a0 = uHx[rA * FS + 8 * k0 + q];
            uint32_t a1 = uHx[rB * FS + 8 * k0 + q];
            uint32_t a2 = uHx[rA * FS + 8 * k0 + q + 4];
            uint32_t a3 = uHx[rB * FS + 8 * k0 + q + 4];
            #pragma unroll
            for (int j = 0; j < 2; j++) {
                uint32_t b0 = uW[(nq + 8 * j + g) * FS + 8 * k0 + q];
                uint32_t b1 = uW[(nq + 8 * j + g) * FS + 8 * k0 + q + 4];
                mma_tf32(aw[j][0], aw[j][1], aw[j][2], aw[j][3], a0, a1, a2, a3, b0, b1);
            }
        }
        float invA = (gnA < N) ? 1.f / fmaxf((float)g_degi[gnA], 1.f) : 0.f;
        float invB = (gnB < N) ? 1.f / fmaxf((float)g_degi[gnB], 1.f) : 0.f;
        #pragma unroll
        for (int j = 0; j < 2; j++) {
            int cb = nq + 8 * j + 2 * q;
            uInp[rA * FS + cb]     = f2tf32(sigm(aw[j][0]) * sAgg[rA * FS + cb]     * invA);
            uInp[rA * FS + cb + 1] = f2tf32(sigm(aw[j][1]) * sAgg[rA * FS + cb + 1] * invA);
            uInp[rB * FS + cb]     = f2tf32(sigm(aw[j][2]) * sAgg[rB * FS + cb]     * invB);
            uInp[rB * FS + cb + 1] = f2tf32(sigm(aw[j][3]) * sAgg[rB * FS + cb + 1] * invB);
        }
    }
    __syncthreads();

    // ---- GI = inp @ Wih^T ; GH = hx @ Whh^T : register accumulators ----
    float accI[3][2][4], accH[3][2][4];
    for (int c = 0; c < 3; c++) {
        for (int idx = tx; idx < 4096; idx += 512) {
            int o = idx >> 6, k = idx & 63;
            uW[o * FS + k]        = g_wihu[c * 4096 + idx];
            uW[4352 + o * FS + k] = g_whhu[c * 4096 + idx];
        }
        __syncthreads();
        #pragma unroll
        for (int j = 0; j < 2; j++)
            #pragma unroll
            for (int v = 0; v < 4; v++) { accI[c][j][v] = 0.f; accH[c][j][v] = 0.f; }
        #pragma unroll
        for (int k0 = 0; k0 < 8; k0++) {
            uint32_t aI0 = uInp[rA * FS + 8 * k0 + q];
            uint32_t aI1 = uInp[rB * FS + 8 * k0 + q];
            uint32_t aI2 = uInp[rA * FS + 8 * k0 + q + 4];
            uint32_t aI3 = uInp[rB * FS + 8 * k0 + q + 4];
            uint32_t aH0 = uHx[rA * FS + 8 * k0 + q];
            uint32_t aH1 = uHx[rB * FS + 8 * k0 + q];
            uint32_t aH2 = uHx[rA * FS + 8 * k0 + q + 4];
            uint32_t aH3 = uHx[rB * FS + 8 * k0 + q + 4];
            #pragma unroll
            for (int j = 0; j < 2; j++) {
                int brow = (nq + 8 * j + g) * FS + 8 * k0 + q;
                uint32_t b0 = uW[brow], b1 = uW[brow + 4];
                mma_tf32(accI[c][j][0], accI[c][j][1], accI[c][j][2], accI[c][j][3],
                         aI0, aI1, aI2, aI3, b0, b1);
                uint32_t c0 = uW[4352 + brow], c1 = uW[4352 + brow + 4];
                mma_tf32(accH[c][j][0], accH[c][j][1], accH[c][j][2], accH[c][j][3],
                         aH0, aH1, aH2, aH3, c0, c1);
            }
        }
        __syncthreads();
    }

    // ---- instance-norm stats ----
    {
        float sIA = 0.f, qIA = 0.f, sIB = 0.f, qIB = 0.f;
        float sHA = 0.f, qHA = 0.f, sHB = 0.f, qHB = 0.f;
        #pragma unroll
        for (int c = 0; c < 3; c++)
            #pragma unroll
            for (int j = 0; j < 2; j++) {
                float a0 = accI[c][j][0], a1 = accI[c][j][1];
                float a2 = accI[c][j][2], a3 = accI[c][j][3];
                sIA += a0 + a1; qIA += a0 * a0 + a1 * a1;
                sIB += a2 + a3; qIB += a2 * a2 + a3 * a3;
                float h0 = accH[c][j][0], h1 = accH[c][j][1];
                float h2 = accH[c][j][2], h3 = accH[c][j][3];
                sHA += h0 + h1; qHA += h0 * h0 + h1 * h1;
                sHB += h2 + h3; qHB += h2 * h2 + h3 * h3;
            }
        #pragma unroll
        for (int m = 1; m <= 2; m <<= 1) {
            sIA += __shfl_xor_sync(0xffffffffu, sIA, m);
            qIA += __shfl_xor_sync(0xffffffffu, qIA, m);
            sIB += __shfl_xor_sync(0xffffffffu, sIB, m);
            qIB += __shfl_xor_sync(0xffffffffu, qIB, m);
            sHA += __shfl_xor_sync(0xffffffffu, sHA, m);
            qHA += __shfl_xor_sync(0xffffffffu, qHA, m);
            sHB += __shfl_xor_sync(0xffffffffu, sHB, m);
            qHB += __shfl_xor_sync(0xffffffffu, qHB, m);
        }
        if (q == 0) {
            float* rdA = sRed + (qt * 64 + rA) * 4;
            rdA[0] = sIA; rdA[1] = qIA; rdA[2] = sHA; rdA[3] = qHA;
            float* rdB = sRed + (qt * 64 + rB) * 4;
            rdB[0] = sIB; rdB[1] = qIB; rdB[2] = sHB; rdB[3] = qHB;
        }
    }
    __syncthreads();
    if (tx < 64) {
        float sI = 0.f, qI = 0.f, sH = 0.f, qH = 0.f;
        #pragma unroll
        for (int qt2 = 0; qt2 < 4; qt2++) {
            const float* rd = sRed + (qt2 * 64 + tx) * 4;
            sI += rd[0]; qI += rd[1]; sH += rd[2]; qH += rd[3];
        }
        float muI = sI * (1.f / 192.f);
        float varI = qI * (1.f / 192.f) - muI * muI;
        float muH = sH * (1.f / 192.f);
        float varH = qH * (1.f / 192.f) - muH * muH;
        sStat[tx * 4 + 0] = muI;
        sStat[tx * 4 + 1] = rsqrtf(varI + 1e-5f);
        sStat[tx * 4 + 2] = muH;
        sStat[tx * 4 + 3] = rsqrtf(varH + 1e-5f);
    }
    __syncthreads();

    // ---- gates + stage ----
    {
        float muIA = sStat[rA * 4 + 0], rsIA = sStat[rA * 4 + 1];
        float muHA = sStat[rA * 4 + 2], rsHA = sStat[rA * 4 + 3];
        float muIB = sStat[rB * 4 + 0], rsIB = sStat[rB * 4 + 1];
        float muHB = sStat[rB * 4 + 2], rsHB = sStat[rB * 4 + 3];
        #pragma unroll
        for (int j = 0; j < 2; j++) {
            #pragma unroll
            for (int v = 0; v < 2; v++) {
                int cb = nq + 8 * j + 2 * q + v;
                float b_r = sBih[cb],       c_r = sBhh[cb];
                float b_i = sBih[64 + cb],  c_i = sBhh[64 + cb];
                float b_n = sBih[128 + cb], c_n = sBhh[128 + cb];
                {
                    float i_r = (accI[0][j][v] - muIA) * rsIA;
                    float i_i = (accI[1][j][v] - muIA) * rsIA;
                    float i_n = (accI[2][j][v] - muIA) * rsIA;
                    float h_r = (accH[0][j][v] - muHA) * rsHA;
                    float h_i = (accH[1][j][v] - muHA) * rsHA;
                    float h_n = (accH[2][j][v] - muHA) * rsHA;
                    float r  = sigm(i_r + b_r + h_r + c_r);
                    float z  = sigm(i_i + b_i + h_i + c_i);
                    float ng = tanhf(i_n + b_n + r * (h_n + c_n));
                    float hxo = sHx32[rA * FS + cb];
                    sOut[rA * FS + cb] = ng + z * (hxo - ng);
                }
                {
                    float i_r = (accI[0][j][v + 2] - muIB) * rsIB;
                    float i_i = (accI[1][j][v + 2] - muIB) * rsIB;
                    float i_n = (accI[2][j][v + 2] - muIB) * rsIB;
                    float h_r = (accH[0][j][v + 2] - muHB) * rsHB;
                    float h_i = (accH[1][j][v + 2] - muHB) * rsHB;
                    float h_n = (accH[2][j][v + 2] - muHB) * rsHB;
                    float r  = sigm(i_r + b_r + h_r + c_r);
                    float z  = sigm(i_i + b_i + h_i + c_i);
                    float ng = tanhf(i_n + b_n + r * (h_n + c_n));
                    float hxo = sHx32[rB * FS + cb];
                    sOut[rB * FS + cb] = ng + z * (hxo - ng);
                }
            }
        }
    }
    __syncthreads();

    // ---- coalesced write of new hx ----
    for (int idx = tx; idx < 4096; idx += 512) {
        int n = idx >> 6, k = idx & 63;
        if (n0 + n < N)
            out[(size_t)(n0 + n) * 256 + toff + 64 + k] = sOut[n * FS + k];
    }
}

// ---------------- launcher ----------------
extern "C" void kernel_launch(void* const* d_in, const int* in_sizes, int n_in,
                              void* d_out, int out_size)
{
    const float* hx  = (const float*)d_in[0];
    const void*  eix = d_in[1];
    const float* ef  = (const float*)d_in[2];
    const float* fW1 = (const float*)d_in[3];
    const float* fb1 = (const float*)d_in[4];
    const float* fW2 = (const float*)d_in[5];
    const float* fb2 = (const float*)d_in[6];
    const float* fW3 = (const float*)d_in[7];
    const float* fb3 = (const float*)d_in[8];
    const float* Wih = (const float*)d_in[9];
    const float* Whh = (const float*)d_in[10];
    const float* bih = (const float*)d_in[11];
    const float* bhh = (const float*)d_in[12];
    const float* Wig = (const float*)d_in[13];
    const float* big = (const float*)d_in[14];
    float* out = (float*)d_out;

    const int N = in_sizes[0] / 64;
    const int E = in_sizes[2] / 13;
    const int nb = (N + 1023) / 1024;

    cudaFuncSetAttribute(fnet_mma_kernel, cudaFuncAttributeMaxDynamicSharedMemorySize, FNET_SMEM);
    cudaFuncSetAttribute(node_mma_kernel, cudaFuncAttributeMaxDynamicSharedMemorySize, NODE_SMEM);

    detect_kernel<<<1, 256>>>((const int*)eix);
    prep_kernel<<<(12288 + 255) / 256, 256>>>(fW1, fW2, fW3, Wig, Wih, Whh);
    copy_hx_kernel<<<(N * 64 + 255) / 256, 256>>>(hx, out, N);
    zero_cnt_kernel<<<(N + 255) / 256, 256>>>(N);
    degi_kernel<<<(E + 255) / 256, 256>>>(eix, E);
    scan1_kernel<<<nb, 256>>>(N);
    scan2_kernel<<<1, 32>>>(nb);
    scan3_kernel<<<(N + 255) / 256, 256>>>(N);
    bin_kernel<<<(E + 255) / 256, 256>>>(eix, E);
    fnet_mma_kernel<<<(E + 255) / 256, 512, FNET_SMEM>>>(ef, fb1, fb2, fb3, E);

    for (int t = 0; t < 3; t++)
        node_mma_kernel<<<(N + 63) / 64, 512, NODE_SMEM>>>(out, bih, bhh, big, t, N);
}